// round 13
// baseline (speedup 1.0000x reference)
#include <cuda_runtime.h>
#include <cuda_fp16.h>
#include <cstdint>

typedef unsigned short u16;
typedef unsigned int u32;

#define BATCH 32
#define SEQ   2048
#define STATE 64
#define LAT   128
#define ENC   256
#define IND   320
#define NPOS  (BATCH*SEQ)
#define NCHUNK 64
#define CLEN   32

// ---------------- device scratch ----------------
__device__ float g_sum[LAT];
__device__ float g_sumsq[LAT];
__device__ float g_z0[BATCH*LAT];
__device__ float g_h0[BATCH*LAT];
__device__ float g_Ap0[LAT*LAT];
__device__ float g_Ap1[LAT*LAT];
__device__ float g_lend[NCHUNK*BATCH*LAT];
__device__ float g_sk[NCHUNK*BATCH*LAT];
__device__ u16 g_a1[(size_t)NPOS*ENC];
__device__ u16 g_a2[(size_t)NPOS*ENC];
__device__ u16 g_z1[(size_t)NPOS*LAT];
__device__ __align__(16) u16 g_we0[256*1*72];
__device__ __align__(16) u16 g_we1[256*4*72];
__device__ __align__(16) u16 g_we2[128*4*72];
__device__ __align__(16) u16 g_wd0[256*2*72];
__device__ __align__(16) u16 g_wd1[256*4*72];
__device__ __align__(16) u16 g_wd2[64*4*72];
__device__ __align__(16) u16 g_Aimg[128*2*72];   // A transposed fp16 image for scan

// ---------------- helpers ----------------
__device__ __forceinline__ u32 smem_u32(const void* p) {
    u32 a;
    asm("{ .reg .u64 t; cvta.to.shared.u64 t, %1; cvt.u32.u64 %0, t; }" : "=r"(a) : "l"(p));
    return a;
}
#define LDSM4(r, a) \
    asm volatile("ldmatrix.sync.aligned.m8n8.x4.shared.b16 {%0,%1,%2,%3}, [%4];" \
        : "=r"((r)[0]), "=r"((r)[1]), "=r"((r)[2]), "=r"((r)[3]) : "r"(a))
#define MMA(d, a, b) \
    asm volatile("mma.sync.aligned.m16n8k16.row.col.f32.f16.f16.f32 " \
        "{%0,%1,%2,%3},{%4,%5,%6,%7},{%8,%9},{%0,%1,%2,%3};" \
        : "+f"((d)[0]), "+f"((d)[1]), "+f"((d)[2]), "+f"((d)[3]) \
        : "r"((a)[0]), "r"((a)[1]), "r"((a)[2]), "r"((a)[3]), "r"((b)[0]), "r"((b)[1]))
#define CPA16(dst, src) asm volatile("cp.async.cg.shared.global [%0], [%1], 16;" :: "r"(dst), "l"(src))
#define CPA_FLUSH() asm volatile("cp.async.commit_group;\ncp.async.wait_group 0;" ::: "memory")

__device__ __forceinline__ u16 f2h(float v) { __half h = __float2half(v); return *(u16*)&h; }
__device__ __forceinline__ u32 pack2h(float a, float b) {
    return (u32)f2h(a) | ((u32)f2h(b) << 16);
}

// ---------------- small kernels ----------------
__global__ void k_init() {
    int t = threadIdx.x;
    if (t < LAT) { g_sum[t] = 0.f; g_sumsq[t] = 0.f; }
}

__global__ void k_sq(const float* __restrict__ Aw, int step) {
    extern __shared__ float S[];
    const float* src = (step == 0) ? Aw : ((step & 1) ? g_Ap0 : g_Ap1);
    float* dst = (step & 1) ? g_Ap1 : g_Ap0;
    int t = threadIdx.x;
    for (int i = t; i < LAT*LAT; i += 512) S[i] = src[i];
    __syncthreads();
    int base = blockIdx.x * 512 + t;
    int i = base >> 7, j = base & 127;
    float acc = 0.f;
#pragma unroll 8
    for (int k = 0; k < LAT; k++) acc = fmaf(S[i*LAT + k], S[k*LAT + j], acc);
    dst[base] = acc;
}

__global__ void k_prepw(const float* __restrict__ W, int K, int N, int NT,
                        u16* __restrict__ oh) {
    int idx = blockIdx.x * 256 + threadIdx.x;
    if (idx >= K * N) return;
    int k = idx / N, n = idx % N;
    int NCH = K >> 6;
    int nt = n / NT, nloc = n % NT, c = k >> 6, kl = k & 63;
    size_t d = ((size_t)(nt * NCH + c) * NT + nloc) * 72 + kl;
    oh[d] = f2h(W[idx]);
}

// ---------------- HMMA GEMM: pure fp16, single pass (unchanged from R12) ----------------
template<int K, int NT, int EPI, int ASRC>
__global__ void __launch_bounds__(256, 2) k_gemm(
    const float* __restrict__ A32, const u16* __restrict__ Ax, int lda,
    const u16* __restrict__ Wx,
    const float* __restrict__ bias,
    u16* __restrict__ Ox, float* __restrict__ outF, int ldo)
{
    constexpr int KC  = 64;
    constexpr int NCH = K / KC;
    constexpr int SMA = 128 * 144;
    constexpr int SMW = NT * 144;
    constexpr int SB  = SMA + SMW;
    constexpr int MT  = (NT == 128) ? 2 : 1;
    constexpr int WM  = (NT == 128) ? 4 : 8;

    extern __shared__ char sm[];
    u32 sb = smem_u32(sm);
    int tid = threadIdx.x, wid = tid >> 5, l = tid & 31;
    int wm = wid % WM, wn = wid / WM;
    int tile = blockIdx.x, nt = blockIdx.y, nt0 = nt * NT;
    int RW = wm * (MT * 16);

    float* sbias = (float*)(sm + SB);
    float* ssum  = (float*)(sm + SB + 512);
    float* ssq   = (float*)(sm + SB + 1024);
    if (tid < NT) sbias[tid] = bias[nt0 + tid];
    if (EPI == 1 && tid < 128) { ssum[tid] = 0.f; ssq[tid] = 0.f; }

    float acc[MT][8][4];
#pragma unroll
    for (int mt = 0; mt < MT; mt++)
#pragma unroll
        for (int n = 0; n < 8; n++)
#pragma unroll
            for (int i = 0; i < 4; i++) acc[mt][n][i] = 0.f;

    u32 aoff = (RW + (l & 15)) * 144 + (l >> 4) * 16;
    u32 boff = (wn*64 + (l & 7) + ((l >> 4) * 8)) * 144 + (((l >> 3) & 1) * 16);
    u32 sA = sb, sW = sb + SMA;

    for (int c = 0; c < NCH; c++) {
        __syncthreads();
        {
            const u16* wp = Wx + (size_t)(nt * NCH + c) * NT * 72;
#pragma unroll
            for (int i = tid; i < NT * 9; i += 256)
                CPA16(sW + i*16, wp + i*8);
        }
        if (ASRC == 1) {
#pragma unroll
            for (int i = tid; i < 1024; i += 256) {
                int row = i >> 3, seg = i & 7;
                size_t go = (size_t)(tile*128 + row) * lda + c*KC + seg*8;
                CPA16(sA + row*144 + seg*16, Ax + go);
            }
        } else {
            int r = tid & 127, kh = (tid >> 7) * 32;
            const float* ap = A32 + (size_t)(tile*128 + r) * lda + c*KC + kh;
#pragma unroll
            for (int j = 0; j < 4; j++) {
                float4 f0 = *(const float4*)(ap + j*8);
                float4 f1 = *(const float4*)(ap + j*8 + 4);
                float f[8] = {f0.x,f0.y,f0.z,f0.w,f1.x,f1.y,f1.z,f1.w};
                union { u16 us[8]; uint4 u; } ph;
#pragma unroll
                for (int q = 0; q < 8; q++) ph.us[q] = f2h(f[q]);
                *(uint4*)(sm + r*144 + (kh + j*8)*2) = ph.u;
            }
        }
        CPA_FLUSH();
        __syncthreads();
#pragma unroll
        for (int ks = 0; ks < 4; ks++) {
            int k2 = ks * 32;
            u32 af[MT][4], bf[4][4];
#pragma unroll
            for (int mt = 0; mt < MT; mt++) LDSM4(af[mt], sA + aoff + mt*2304 + k2);
#pragma unroll
            for (int p = 0; p < 4; p++)     LDSM4(bf[p], sW + boff + p*2304 + k2);
#pragma unroll
            for (int mt = 0; mt < MT; mt++)
#pragma unroll
                for (int p = 0; p < 4; p++) {
                    MMA(acc[mt][2*p],   af[mt], bf[p]);
                    MMA(acc[mt][2*p+1], af[mt], &bf[p][2]);
                }
        }
    }

    int g = l >> 2, tg = l & 3;
#pragma unroll
    for (int mt = 0; mt < MT; mt++) {
        int row = tile*128 + RW + mt*16 + g;
#pragma unroll
        for (int n = 0; n < 8; n++) {
            int colL = wn*64 + n*8 + tg*2;
            float b0 = sbias[colL], b1 = sbias[colL + 1];
            float v0 = acc[mt][n][0] + b0, v1 = acc[mt][n][1] + b1;
            float v2 = acc[mt][n][2] + b0, v3 = acc[mt][n][3] + b1;
            if (EPI != 2) {
                v0 = fmaxf(v0, 0.f); v1 = fmaxf(v1, 0.f);
                v2 = fmaxf(v2, 0.f); v3 = fmaxf(v3, 0.f);
            }
            if (EPI == 1) {
                atomicAdd(&ssum[colL],     v0 + v2);
                atomicAdd(&ssq[colL],      v0*v0 + v2*v2);
                atomicAdd(&ssum[colL + 1], v1 + v3);
                atomicAdd(&ssq[colL + 1],  v1*v1 + v3*v3);
                if (((tile & 15) == 0) && g == 0 && wm == 0 && mt == 0) {
                    g_z0[(tile >> 4) * LAT + colL]     = v0;
                    g_z0[(tile >> 4) * LAT + colL + 1] = v1;
                }
            } else if (EPI == 0) {
                size_t o0 = (size_t)row * ldo + nt0 + colL;
                size_t o1 = (size_t)(row + 8) * ldo + nt0 + colL;
                *(u32*)&Ox[o0] = pack2h(v0, v1);
                *(u32*)&Ox[o1] = pack2h(v2, v3);
            } else {
                *(float2*)&outF[(size_t)row * ldo + nt0 + colL]       = make_float2(v0, v1);
                *(float2*)&outF[(size_t)(row + 8) * ldo + nt0 + colL] = make_float2(v2, v3);
            }
        }
    }
    if (EPI == 1) {
        __syncthreads();
        if (tid < 128) {
            atomicAdd(&g_sum[tid],   ssum[tid]);
            atomicAdd(&g_sumsq[tid], ssq[tid]);
        }
    }
}

// ---------------- BN finalize ----------------
__global__ void k_fin(const float* __restrict__ gamma, const float* __restrict__ beta)
{
    int j = threadIdx.x;
    float inv = 1.f / (float)NPOS;
    float m  = g_sum[j] * inv;
    float v  = g_sumsq[j] * inv - m * m;
    float rs = rsqrtf(v + 1e-5f);
    float ga = gamma[j], be = beta[j];
    for (int b = 0; b < BATCH; b++) {
        float z = g_z0[b*LAT + j];
        g_h0[b*LAT + j] = (z - m) * rs * ga + be;
    }
}

// ---------------- MMA scan: h_{t+1} = h_t @ A + u_t*d, A resident in registers ----------------
// PASS 0: zero-init, final state -> g_lend ; PASS 1: init from g_sk, every state -> g_z1 (fp16)
template<int PASS>
__global__ void __launch_bounds__(256) k_scan(
    const float* __restrict__ in, const float* __restrict__ Bd)
{
    // smem layout (bytes)
    constexpr int SM_A   = 0;          // 2 chunks * 128 rows * 144 = 36864
    constexpr int SM_H   = 36864;      // 2 * 16 * 272 = 8704
    constexpr int SM_BU  = 45568;      // 16 * 132 floats = 8448
    constexpr int SM_D   = 54016;      // 128 floats
    extern __shared__ char sm[];
    u32 sb = smem_u32(sm);

    int tid = threadIdx.x, wid = tid >> 5, l = tid & 31;
    int chunk = blockIdx.x, b0 = blockIdx.y * 16;
    int g = l >> 2, tg = l & 3;
    int wcol = wid * 16;

    // load A image (both k-chunks) + d
    for (int i = tid; i < 2304; i += 256)
        CPA16(sb + SM_A + i*16, g_Aimg + i*8);
    if (tid < 128) ((float*)(sm + SM_D))[tid] = fminf(fmaxf(Bd[tid], -0.95f), 0.95f);
    CPA_FLUSH();
    __syncthreads();

    // resident A fragments (B-operand): warp covers n cols [wcol, wcol+16)
    u32 bf[8][4];
    u32 boffb = (u32)((wcol + (l & 7) + ((l >> 4) * 8)) * 144 + (((l >> 3) & 1) * 16));
#pragma unroll
    for (int ks = 0; ks < 8; ks++)
        LDSM4(bf[ks], sb + SM_A + (ks >> 2) * 18432 + boffb + (ks & 3) * 32);

    // init h buffer 0
    {
        int row = tid >> 4, cg = (tid & 15) * 8;
        u32 hdst = sb + SM_H + row * 272 + cg * 2;
        if (PASS == 1) {
            const float* sp = &g_sk[(size_t)(chunk * BATCH + b0 + row) * LAT + cg];
            float4 f0 = *(const float4*)sp, f1 = *(const float4*)(sp + 4);
            u32 p0 = pack2h(f0.x, f0.y), p1 = pack2h(f0.z, f0.w);
            u32 p2 = pack2h(f1.x, f1.y), p3 = pack2h(f1.z, f1.w);
            *(uint4*)(sm + (hdst - sb)) = make_uint4(p0, p1, p2, p3);
        } else {
            *(uint4*)(sm + (hdst - sb)) = make_uint4(0, 0, 0, 0);
        }
    }
    __syncthreads();

    const float* sd = (const float*)(sm + SM_D);
    float* sbu = (float*)(sm + SM_BU);
    u32 aoff = (u32)((l & 15) * 272 + (l >> 4) * 16);
    int cur = 0;
    int t0 = chunk * CLEN;
    float c0[4], c1[4];

    for (int t = t0; t < t0 + CLEN; t++) {
        // stage bu tile [16][128] (coalesced)
#pragma unroll
        for (int i = tid; i < 2048; i += 256) {
            int row = i >> 7, col = i & 127;
            sbu[row * 132 + col] =
                in[((size_t)(b0 + row) * SEQ + t) * IND + (STATE + LAT) + col] * sd[col];
        }
        __syncthreads();

        // C init from bu
        {
            float2 a0 = *(float2*)&sbu[g * 132 + wcol + tg*2];
            float2 a1 = *(float2*)&sbu[(g + 8) * 132 + wcol + tg*2];
            float2 a2 = *(float2*)&sbu[g * 132 + wcol + 8 + tg*2];
            float2 a3 = *(float2*)&sbu[(g + 8) * 132 + wcol + 8 + tg*2];
            c0[0] = a0.x; c0[1] = a0.y; c0[2] = a1.x; c0[3] = a1.y;
            c1[0] = a2.x; c1[1] = a2.y; c1[2] = a3.x; c1[3] = a3.y;
        }

        // h @ A
        u32 hbase = sb + SM_H + cur * 4352;
#pragma unroll
        for (int ks = 0; ks < 8; ks++) {
            u32 af[4];
            LDSM4(af, hbase + aoff + ks * 32);
            MMA(c0, af, bf[ks]);
            MMA(c1, af, &bf[ks][2]);
        }

        // store new h (fp16) to alternate buffer; pass1 also writes z1
        u32 hn = sb + SM_H + (cur ^ 1) * 4352;
        u32 p00 = pack2h(c0[0], c0[1]), p01 = pack2h(c0[2], c0[3]);
        u32 p10 = pack2h(c1[0], c1[1]), p11 = pack2h(c1[2], c1[3]);
        *(u32*)(sm + (hn - sb) + g * 272 + (wcol + tg*2) * 2)       = p00;
        *(u32*)(sm + (hn - sb) + (g + 8) * 272 + (wcol + tg*2) * 2) = p01;
        *(u32*)(sm + (hn - sb) + g * 272 + (wcol + 8 + tg*2) * 2)       = p10;
        *(u32*)(sm + (hn - sb) + (g + 8) * 272 + (wcol + 8 + tg*2) * 2) = p11;
        if (PASS == 1) {
            size_t r0 = ((size_t)(b0 + g) * SEQ + t) * LAT;
            size_t r1 = ((size_t)(b0 + g + 8) * SEQ + t) * LAT;
            *(u32*)&g_z1[r0 + wcol + tg*2]     = p00;
            *(u32*)&g_z1[r1 + wcol + tg*2]     = p01;
            *(u32*)&g_z1[r0 + wcol + 8 + tg*2] = p10;
            *(u32*)&g_z1[r1 + wcol + 8 + tg*2] = p11;
        }
        __syncthreads();
        cur ^= 1;
    }

    if (PASS == 0) {
        // final state (fp32 C regs) -> g_lend
        size_t r0 = (size_t)(chunk * BATCH + b0 + g) * LAT;
        size_t r1 = (size_t)(chunk * BATCH + b0 + g + 8) * LAT;
        *(float2*)&g_lend[r0 + wcol + tg*2]     = make_float2(c0[0], c0[1]);
        *(float2*)&g_lend[r1 + wcol + tg*2]     = make_float2(c0[2], c0[3]);
        *(float2*)&g_lend[r0 + wcol + 8 + tg*2] = make_float2(c1[0], c1[1]);
        *(float2*)&g_lend[r1 + wcol + 8 + tg*2] = make_float2(c1[2], c1[3]);
    }
}

// ---------------- boundary scan via A^32 ----------------
__global__ void __launch_bounds__(128) k_bound()
{
    extern __shared__ float smf[];
    float* As = smf;
    float* sv = smf + LAT * LAT;
    int j = threadIdx.x;
    int b = blockIdx.x;
    for (int idx = j; idx < LAT * LAT; idx += 128) As[idx] = g_Ap0[idx];
    float s = g_h0[b * LAT + j];
    for (int k = 0; k < NCHUNK; k++) {
        g_sk[(k * BATCH + b) * LAT + j] = s;
        sv[j] = s;
        __syncthreads();
        float acc = g_lend[(k * BATCH + b) * LAT + j];
#pragma unroll 8
        for (int m4 = 0; m4 < LAT; m4 += 4) {
            float a0 = As[(m4+0)*LAT + j], a1 = As[(m4+1)*LAT + j];
            float a2 = As[(m4+2)*LAT + j], a3 = As[(m4+3)*LAT + j];
            float4 h = *(const float4*)&sv[m4];
            acc = fmaf(h.x, a0, fmaf(h.y, a1, fmaf(h.z, a2, fmaf(h.w, a3, acc))));
        }
        __syncthreads();
        s = acc;
    }
}

// ---------------- launch ----------------
extern "C" void kernel_launch(void* const* d_in, const int* in_sizes, int n_in,
                              void* d_out, int out_size)
{
    const float* in  = (const float*)d_in[0];
    const float* ew0 = (const float*)d_in[1];
    const float* eb0 = (const float*)d_in[2];
    const float* ew1 = (const float*)d_in[3];
    const float* eb1 = (const float*)d_in[4];
    const float* ew2 = (const float*)d_in[5];
    const float* eb2 = (const float*)d_in[6];
    const float* gam = (const float*)d_in[7];
    const float* bet = (const float*)d_in[8];
    const float* Aw  = (const float*)d_in[9];
    const float* Bd  = (const float*)d_in[10];
    const float* dw0 = (const float*)d_in[11];
    const float* db0 = (const float*)d_in[12];
    const float* dw1 = (const float*)d_in[13];
    const float* db1 = (const float*)d_in[14];
    const float* dw2 = (const float*)d_in[15];
    const float* db2 = (const float*)d_in[16];
    float* out = (float*)d_out;

    u16 *a1, *a2, *z1, *we0, *we1, *we2, *wd0, *wd1, *wd2, *Aimg;
    cudaGetSymbolAddress((void**)&a1, g_a1);
    cudaGetSymbolAddress((void**)&a2, g_a2);
    cudaGetSymbolAddress((void**)&z1, g_z1);
    cudaGetSymbolAddress((void**)&we0, g_we0);
    cudaGetSymbolAddress((void**)&we1, g_we1);
    cudaGetSymbolAddress((void**)&we2, g_we2);
    cudaGetSymbolAddress((void**)&wd0, g_wd0);
    cudaGetSymbolAddress((void**)&wd1, g_wd1);
    cudaGetSymbolAddress((void**)&wd2, g_wd2);
    cudaGetSymbolAddress((void**)&Aimg, g_Aimg);

    const int SM128 = 38400;
    const int SM64  = 29184;
    const int SMSC  = 54528;

    cudaFuncSetAttribute(k_sq,    cudaFuncAttributeMaxDynamicSharedMemorySize, 65536);
    cudaFuncSetAttribute(k_bound, cudaFuncAttributeMaxDynamicSharedMemorySize, 66560);
    cudaFuncSetAttribute(k_scan<0>, cudaFuncAttributeMaxDynamicSharedMemorySize, SMSC);
    cudaFuncSetAttribute(k_scan<1>, cudaFuncAttributeMaxDynamicSharedMemorySize, SMSC);
    cudaFuncSetAttribute(k_gemm<64,128,0,0>,  cudaFuncAttributeMaxDynamicSharedMemorySize, SM128);
    cudaFuncSetAttribute(k_gemm<256,128,0,1>, cudaFuncAttributeMaxDynamicSharedMemorySize, SM128);
    cudaFuncSetAttribute(k_gemm<256,128,1,1>, cudaFuncAttributeMaxDynamicSharedMemorySize, SM128);
    cudaFuncSetAttribute(k_gemm<128,128,0,1>, cudaFuncAttributeMaxDynamicSharedMemorySize, SM128);
    cudaFuncSetAttribute(k_gemm<256,64,2,1>,  cudaFuncAttributeMaxDynamicSharedMemorySize, SM64);

    static cudaStream_t sB = nullptr;
    static cudaEvent_t evF = nullptr, evB = nullptr;
    if (!sB) {
        cudaStreamCreateWithFlags(&sB, cudaStreamNonBlocking);
        cudaEventCreateWithFlags(&evF, cudaEventDisableTiming);
        cudaEventCreateWithFlags(&evB, cudaEventDisableTiming);
    }

    cudaEventRecord(evF, 0);

    // ---- stream 0: encoder ----
    k_init<<<1, 128>>>();
    k_prepw<<<(64*256+255)/256,  256>>>(ew0, 64, 256, 128, we0);
    k_prepw<<<(256*256+255)/256, 256>>>(ew1, 256, 256, 128, we1);
    k_prepw<<<(256*128+255)/256, 256>>>(ew2, 256, 128, 128, we2);
    k_gemm<64,128,0,0><<<dim3(512,2), 256, SM128>>>(in, nullptr, IND,
        we0, eb0, a1, nullptr, 256);
    k_gemm<256,128,0,1><<<dim3(512,2), 256, SM128>>>(nullptr, a1, 256,
        we1, eb1, a2, nullptr, 256);
    k_gemm<256,128,1,1><<<dim3(512,1), 256, SM128>>>(nullptr, a2, 256,
        we2, eb2, nullptr, nullptr, 0);
    k_fin<<<1, 128>>>(gam, bet);

    // ---- stream B: A prep + MMA pass0, then A^32 chain, then dec preps ----
    cudaStreamWaitEvent(sB, evF, 0);
    k_prepw<<<(128*128+255)/256, 256, 0, sB>>>(Aw, 128, 128, 128, Aimg);
    k_scan<0><<<dim3(NCHUNK, 2), 256, SMSC, sB>>>(in, Bd);
    for (int s = 0; s < 5; s++) k_sq<<<32, 512, 65536, sB>>>(Aw, s);
    k_prepw<<<(128*256+255)/256, 256, 0, sB>>>(dw0, 128, 256, 128, wd0);
    k_prepw<<<(256*256+255)/256, 256, 0, sB>>>(dw1, 256, 256, 128, wd1);
    k_prepw<<<(256*64+255)/256,  256, 0, sB>>>(dw2, 256, 64, 64, wd2);
    cudaEventRecord(evB, sB);

    // ---- join, serial tail ----
    cudaStreamWaitEvent(0, evB, 0);
    k_bound<<<BATCH, 128, 66560>>>();
    k_scan<1><<<dim3(NCHUNK, 2), 256, SMSC>>>(in, Bd);
    k_gemm<128,128,0,1><<<dim3(512,2), 256, SM128>>>(nullptr, z1, 128,
        wd0, db0, a1, nullptr, 256);
    k_gemm<256,128,0,1><<<dim3(512,2), 256, SM128>>>(nullptr, a1, 256,
        wd1, db1, a2, nullptr, 256);
    k_gemm<256,64,2,1><<<dim3(512,1), 256, SM64>>>(nullptr, a2, 256,
        wd2, db2, nullptr, out, 64);
}

// round 14
// speedup vs baseline: 1.5615x; 1.5615x over previous
#include <cuda_runtime.h>
#include <cuda_fp16.h>
#include <cstdint>

typedef unsigned short u16;
typedef unsigned int u32;

#define BATCH 32
#define SEQ   2048
#define STATE 64
#define LAT   128
#define ENC   256
#define IND   320
#define NPOS  (BATCH*SEQ)
#define NCHUNK 64
#define CLEN   32

// ---------------- device scratch ----------------
__device__ float g_sum[LAT];
__device__ float g_sumsq[LAT];
__device__ float g_z0[BATCH*LAT];
__device__ float g_h0[BATCH*LAT];
__device__ float g_Ap0[LAT*LAT];
__device__ float g_Ap1[LAT*LAT];
__device__ float g_lend[NCHUNK*BATCH*LAT];
__device__ float g_sk[NCHUNK*BATCH*LAT];
__device__ u16 g_a1[(size_t)NPOS*ENC];
__device__ u16 g_a2[(size_t)NPOS*ENC];
__device__ u16 g_z1[(size_t)NPOS*LAT];
__device__ __align__(16) u16 g_we0[256*1*72];
__device__ __align__(16) u16 g_we1[256*4*72];
__device__ __align__(16) u16 g_we2[128*4*72];
__device__ __align__(16) u16 g_wd0[256*2*72];
__device__ __align__(16) u16 g_wd1[256*4*72];
__device__ __align__(16) u16 g_wd2[64*4*72];
__device__ __align__(16) u16 g_Aimg[128*2*72];   // A transposed fp16 image for scan

// ---------------- helpers ----------------
__device__ __forceinline__ u32 smem_u32(const void* p) {
    u32 a;
    asm("{ .reg .u64 t; cvta.to.shared.u64 t, %1; cvt.u32.u64 %0, t; }" : "=r"(a) : "l"(p));
    return a;
}
#define LDSM4(r, a) \
    asm volatile("ldmatrix.sync.aligned.m8n8.x4.shared.b16 {%0,%1,%2,%3}, [%4];" \
        : "=r"((r)[0]), "=r"((r)[1]), "=r"((r)[2]), "=r"((r)[3]) : "r"(a))
#define MMA(d, a, b) \
    asm volatile("mma.sync.aligned.m16n8k16.row.col.f32.f16.f16.f32 " \
        "{%0,%1,%2,%3},{%4,%5,%6,%7},{%8,%9},{%0,%1,%2,%3};" \
        : "+f"((d)[0]), "+f"((d)[1]), "+f"((d)[2]), "+f"((d)[3]) \
        : "r"((a)[0]), "r"((a)[1]), "r"((a)[2]), "r"((a)[3]), "r"((b)[0]), "r"((b)[1]))
#define CPA16(dst, src) asm volatile("cp.async.cg.shared.global [%0], [%1], 16;" :: "r"(dst), "l"(src))
#define CPA_COMMIT()  asm volatile("cp.async.commit_group;" ::: "memory")
#define CPA_WAIT0()   asm volatile("cp.async.wait_group 0;" ::: "memory")
#define CPA_WAIT1()   asm volatile("cp.async.wait_group 1;" ::: "memory")
#define CPA_FLUSH() asm volatile("cp.async.commit_group;\ncp.async.wait_group 0;" ::: "memory")

__device__ __forceinline__ u16 f2h(float v) { __half h = __float2half(v); return *(u16*)&h; }
__device__ __forceinline__ u32 pack2h(float a, float b) {
    return (u32)f2h(a) | ((u32)f2h(b) << 16);
}

// ---------------- small kernels ----------------
__global__ void k_init() {
    int t = threadIdx.x;
    if (t < LAT) { g_sum[t] = 0.f; g_sumsq[t] = 0.f; }
}

__global__ void k_sq(const float* __restrict__ Aw, int step) {
    extern __shared__ float S[];
    const float* src = (step == 0) ? Aw : ((step & 1) ? g_Ap0 : g_Ap1);
    float* dst = (step & 1) ? g_Ap1 : g_Ap0;
    int t = threadIdx.x;
    for (int i = t; i < LAT*LAT; i += 512) S[i] = src[i];
    __syncthreads();
    int base = blockIdx.x * 512 + t;
    int i = base >> 7, j = base & 127;
    float acc = 0.f;
#pragma unroll 8
    for (int k = 0; k < LAT; k++) acc = fmaf(S[i*LAT + k], S[k*LAT + j], acc);
    dst[base] = acc;
}

__global__ void k_prepw(const float* __restrict__ W, int K, int N, int NT,
                        u16* __restrict__ oh) {
    int idx = blockIdx.x * 256 + threadIdx.x;
    if (idx >= K * N) return;
    int k = idx / N, n = idx % N;
    int NCH = K >> 6;
    int nt = n / NT, nloc = n % NT, c = k >> 6, kl = k & 63;
    size_t d = ((size_t)(nt * NCH + c) * NT + nloc) * 72 + kl;
    oh[d] = f2h(W[idx]);
}

// ---------------- HMMA GEMM: pure fp16, single pass ----------------
template<int K, int NT, int EPI, int ASRC>
__global__ void __launch_bounds__(256, 2) k_gemm(
    const float* __restrict__ A32, const u16* __restrict__ Ax, int lda,
    const u16* __restrict__ Wx,
    const float* __restrict__ bias,
    u16* __restrict__ Ox, float* __restrict__ outF, int ldo)
{
    constexpr int KC  = 64;
    constexpr int NCH = K / KC;
    constexpr int SMA = 128 * 144;
    constexpr int SMW = NT * 144;
    constexpr int SB  = SMA + SMW;
    constexpr int MT  = (NT == 128) ? 2 : 1;
    constexpr int WM  = (NT == 128) ? 4 : 8;

    extern __shared__ char sm[];
    u32 sb = smem_u32(sm);
    int tid = threadIdx.x, wid = tid >> 5, l = tid & 31;
    int wm = wid % WM, wn = wid / WM;
    int tile = blockIdx.x, nt = blockIdx.y, nt0 = nt * NT;
    int RW = wm * (MT * 16);

    float* sbias = (float*)(sm + SB);
    float* ssum  = (float*)(sm + SB + 512);
    float* ssq   = (float*)(sm + SB + 1024);
    if (tid < NT) sbias[tid] = bias[nt0 + tid];
    if (EPI == 1 && tid < 128) { ssum[tid] = 0.f; ssq[tid] = 0.f; }

    float acc[MT][8][4];
#pragma unroll
    for (int mt = 0; mt < MT; mt++)
#pragma unroll
        for (int n = 0; n < 8; n++)
#pragma unroll
            for (int i = 0; i < 4; i++) acc[mt][n][i] = 0.f;

    u32 aoff = (RW + (l & 15)) * 144 + (l >> 4) * 16;
    u32 boff = (wn*64 + (l & 7) + ((l >> 4) * 8)) * 144 + (((l >> 3) & 1) * 16);
    u32 sA = sb, sW = sb + SMA;

    for (int c = 0; c < NCH; c++) {
        __syncthreads();
        {
            const u16* wp = Wx + (size_t)(nt * NCH + c) * NT * 72;
#pragma unroll
            for (int i = tid; i < NT * 9; i += 256)
                CPA16(sW + i*16, wp + i*8);
        }
        if (ASRC == 1) {
#pragma unroll
            for (int i = tid; i < 1024; i += 256) {
                int row = i >> 3, seg = i & 7;
                size_t go = (size_t)(tile*128 + row) * lda + c*KC + seg*8;
                CPA16(sA + row*144 + seg*16, Ax + go);
            }
        } else {
            int r = tid & 127, kh = (tid >> 7) * 32;
            const float* ap = A32 + (size_t)(tile*128 + r) * lda + c*KC + kh;
#pragma unroll
            for (int j = 0; j < 4; j++) {
                float4 f0 = *(const float4*)(ap + j*8);
                float4 f1 = *(const float4*)(ap + j*8 + 4);
                float f[8] = {f0.x,f0.y,f0.z,f0.w,f1.x,f1.y,f1.z,f1.w};
                union { u16 us[8]; uint4 u; } ph;
#pragma unroll
                for (int q = 0; q < 8; q++) ph.us[q] = f2h(f[q]);
                *(uint4*)(sm + r*144 + (kh + j*8)*2) = ph.u;
            }
        }
        CPA_FLUSH();
        __syncthreads();
#pragma unroll
        for (int ks = 0; ks < 4; ks++) {
            int k2 = ks * 32;
            u32 af[MT][4], bf[4][4];
#pragma unroll
            for (int mt = 0; mt < MT; mt++) LDSM4(af[mt], sA + aoff + mt*2304 + k2);
#pragma unroll
            for (int p = 0; p < 4; p++)     LDSM4(bf[p], sW + boff + p*2304 + k2);
#pragma unroll
            for (int mt = 0; mt < MT; mt++)
#pragma unroll
                for (int p = 0; p < 4; p++) {
                    MMA(acc[mt][2*p],   af[mt], bf[p]);
                    MMA(acc[mt][2*p+1], af[mt], &bf[p][2]);
                }
        }
    }

    int g = l >> 2, tg = l & 3;
#pragma unroll
    for (int mt = 0; mt < MT; mt++) {
        int row = tile*128 + RW + mt*16 + g;
#pragma unroll
        for (int n = 0; n < 8; n++) {
            int colL = wn*64 + n*8 + tg*2;
            float b0 = sbias[colL], b1 = sbias[colL + 1];
            float v0 = acc[mt][n][0] + b0, v1 = acc[mt][n][1] + b1;
            float v2 = acc[mt][n][2] + b0, v3 = acc[mt][n][3] + b1;
            if (EPI != 2) {
                v0 = fmaxf(v0, 0.f); v1 = fmaxf(v1, 0.f);
                v2 = fmaxf(v2, 0.f); v3 = fmaxf(v3, 0.f);
            }
            if (EPI == 1) {
                atomicAdd(&ssum[colL],     v0 + v2);
                atomicAdd(&ssq[colL],      v0*v0 + v2*v2);
                atomicAdd(&ssum[colL + 1], v1 + v3);
                atomicAdd(&ssq[colL + 1],  v1*v1 + v3*v3);
                if (((tile & 15) == 0) && g == 0 && wm == 0 && mt == 0) {
                    g_z0[(tile >> 4) * LAT + colL]     = v0;
                    g_z0[(tile >> 4) * LAT + colL + 1] = v1;
                }
            } else if (EPI == 0) {
                size_t o0 = (size_t)row * ldo + nt0 + colL;
                size_t o1 = (size_t)(row + 8) * ldo + nt0 + colL;
                *(u32*)&Ox[o0] = pack2h(v0, v1);
                *(u32*)&Ox[o1] = pack2h(v2, v3);
            } else {
                *(float2*)&outF[(size_t)row * ldo + nt0 + colL]       = make_float2(v0, v1);
                *(float2*)&outF[(size_t)(row + 8) * ldo + nt0 + colL] = make_float2(v2, v3);
            }
        }
    }
    if (EPI == 1) {
        __syncthreads();
        if (tid < 128) {
            atomicAdd(&g_sum[tid],   ssum[tid]);
            atomicAdd(&g_sumsq[tid], ssq[tid]);
        }
    }
}

// ---------------- BN finalize ----------------
__global__ void k_fin(const float* __restrict__ gamma, const float* __restrict__ beta)
{
    int j = threadIdx.x;
    float inv = 1.f / (float)NPOS;
    float m  = g_sum[j] * inv;
    float v  = g_sumsq[j] * inv - m * m;
    float rs = rsqrtf(v + 1e-5f);
    float ga = gamma[j], be = beta[j];
    for (int b = 0; b < BATCH; b++) {
        float z = g_z0[b*LAT + j];
        g_h0[b*LAT + j] = (z - m) * rs * ga + be;
    }
}

// ---------------- MMA scan with bu cp.async prefetch ----------------
// PASS 0: zero-init, final state -> g_lend ; PASS 1: init from g_sk, every state -> g_z1 (fp16)
template<int PASS>
__global__ void __launch_bounds__(256) k_scan(
    const float* __restrict__ in, const float* __restrict__ Bd)
{
    // smem layout (bytes)
    constexpr int SM_A   = 0;          // 2304*16 = 36864
    constexpr int SM_H   = 36864;      // 2 * 16 * 272 = 8704
    constexpr int SM_BU  = 45568;      // 2 * 16 rows * 528 = 16896
    constexpr int BUST   = 8448;       // one bu stage
    constexpr int SM_D   = 62464;      // 128 floats
    extern __shared__ char sm[];
    u32 sb = smem_u32(sm);

    int tid = threadIdx.x, wid = tid >> 5, l = tid & 31;
    int chunk = blockIdx.x, b0 = blockIdx.y * 16;
    int g = l >> 2, tg = l & 3;
    int wcol = wid * 16;
    int t0 = chunk * CLEN;

    // prefetch of bu tile for step t into stage s (raw u values, 16 rows x 128 floats)
    auto loadBU = [&](int t, int s) {
        u32 base = sb + SM_BU + s * BUST;
#pragma unroll
        for (int i = tid; i < 512; i += 256) {
            int row = i >> 5, seg = i & 31;
            const float* src = in + ((size_t)(b0 + row) * SEQ + t) * IND + (STATE + LAT) + seg * 4;
            CPA16(base + row * 528 + seg * 16, src);
        }
    };

    // group 0: A image + bu(t0)
    for (int i = tid; i < 2304; i += 256)
        CPA16(sb + SM_A + i*16, g_Aimg + i*8);
    loadBU(t0, 0);
    if (tid < 128) ((float*)(sm + SM_D))[tid] = fminf(fmaxf(Bd[tid], -0.95f), 0.95f);
    CPA_COMMIT();

    // init h buffer 0 (plain smem stores, not dependent on cp.async)
    {
        int row = tid >> 4, cg = (tid & 15) * 8;
        u32 off = SM_H + row * 272 + cg * 2;
        if (PASS == 1) {
            const float* sp = &g_sk[(size_t)(chunk * BATCH + b0 + row) * LAT + cg];
            float4 f0 = *(const float4*)sp, f1 = *(const float4*)(sp + 4);
            *(uint4*)(sm + off) = make_uint4(pack2h(f0.x, f0.y), pack2h(f0.z, f0.w),
                                             pack2h(f1.x, f1.y), pack2h(f1.z, f1.w));
        } else {
            *(uint4*)(sm + off) = make_uint4(0, 0, 0, 0);
        }
    }
    CPA_WAIT0();
    __syncthreads();

    // resident A fragments (B operand)
    u32 bf[8][4];
    u32 boffb = (u32)((wcol + (l & 7) + ((l >> 4) * 8)) * 144 + (((l >> 3) & 1) * 16));
#pragma unroll
    for (int ks = 0; ks < 8; ks++)
        LDSM4(bf[ks], sb + SM_A + (ks >> 2) * 18432 + boffb + (ks & 3) * 32);

    const float* sd = (const float*)(sm + SM_D);
    float da0 = sd[wcol + tg*2],     da1 = sd[wcol + tg*2 + 1];
    float db0 = sd[wcol + 8 + tg*2], db1 = sd[wcol + 8 + tg*2 + 1];
    u32 aoff = (u32)((l & 15) * 272 + (l >> 4) * 16);
    int cur = 0, buf = 0;
    float c0[4], c1[4];

    for (int t = t0; t < t0 + CLEN; t++) {
        bool pre = (t + 1 < t0 + CLEN);
        if (pre) { loadBU(t + 1, buf ^ 1); CPA_COMMIT(); }
        if (pre) CPA_WAIT1(); else CPA_WAIT0();
        __syncthreads();

        // C init from bu * d
        {
            const char* bub = sm + SM_BU + buf * BUST;
            float2 a0 = *(float2*)(bub + g * 528 + (wcol + tg*2) * 4);
            float2 a1 = *(float2*)(bub + (g + 8) * 528 + (wcol + tg*2) * 4);
            float2 a2 = *(float2*)(bub + g * 528 + (wcol + 8 + tg*2) * 4);
            float2 a3 = *(float2*)(bub + (g + 8) * 528 + (wcol + 8 + tg*2) * 4);
            c0[0] = a0.x * da0; c0[1] = a0.y * da1; c0[2] = a1.x * da0; c0[3] = a1.y * da1;
            c1[0] = a2.x * db0; c1[1] = a2.y * db1; c1[2] = a3.x * db0; c1[3] = a3.y * db1;
        }

        // h @ A
        u32 hbase = sb + SM_H + cur * 4352;
#pragma unroll
        for (int ks = 0; ks < 8; ks++) {
            u32 af[4];
            LDSM4(af, hbase + aoff + ks * 32);
            MMA(c0, af, bf[ks]);
            MMA(c1, af, &bf[ks][2]);
        }

        // store new h; pass1 also writes z1
        int hno = SM_H + (cur ^ 1) * 4352;
        u32 p00 = pack2h(c0[0], c0[1]), p01 = pack2h(c0[2], c0[3]);
        u32 p10 = pack2h(c1[0], c1[1]), p11 = pack2h(c1[2], c1[3]);
        *(u32*)(sm + hno + g * 272 + (wcol + tg*2) * 2)           = p00;
        *(u32*)(sm + hno + (g + 8) * 272 + (wcol + tg*2) * 2)     = p01;
        *(u32*)(sm + hno + g * 272 + (wcol + 8 + tg*2) * 2)       = p10;
        *(u32*)(sm + hno + (g + 8) * 272 + (wcol + 8 + tg*2) * 2) = p11;
        if (PASS == 1) {
            size_t r0 = ((size_t)(b0 + g) * SEQ + t) * LAT;
            size_t r1 = ((size_t)(b0 + g + 8) * SEQ + t) * LAT;
            *(u32*)&g_z1[r0 + wcol + tg*2]     = p00;
            *(u32*)&g_z1[r1 + wcol + tg*2]     = p01;
            *(u32*)&g_z1[r0 + wcol + 8 + tg*2] = p10;
            *(u32*)&g_z1[r1 + wcol + 8 + tg*2] = p11;
        }
        __syncthreads();
        cur ^= 1; buf ^= 1;
    }

    if (PASS == 0) {
        size_t r0 = (size_t)(chunk * BATCH + b0 + g) * LAT;
        size_t r1 = (size_t)(chunk * BATCH + b0 + g + 8) * LAT;
        *(float2*)&g_lend[r0 + wcol + tg*2]     = make_float2(c0[0], c0[1]);
        *(float2*)&g_lend[r1 + wcol + tg*2]     = make_float2(c0[2], c0[3]);
        *(float2*)&g_lend[r0 + wcol + 8 + tg*2] = make_float2(c1[0], c1[1]);
        *(float2*)&g_lend[r1 + wcol + 8 + tg*2] = make_float2(c1[2], c1[3]);
    }
}

// ---------------- boundary scan via A^32 ----------------
__global__ void __launch_bounds__(128) k_bound()
{
    extern __shared__ float smf[];
    float* As = smf;
    float* sv = smf + LAT * LAT;
    int j = threadIdx.x;
    int b = blockIdx.x;
    for (int idx = j; idx < LAT * LAT; idx += 128) As[idx] = g_Ap0[idx];
    float s = g_h0[b * LAT + j];
    for (int k = 0; k < NCHUNK; k++) {
        g_sk[(k * BATCH + b) * LAT + j] = s;
        sv[j] = s;
        __syncthreads();
        float acc = g_lend[(k * BATCH + b) * LAT + j];
#pragma unroll 8
        for (int m4 = 0; m4 < LAT; m4 += 4) {
            float a0 = As[(m4+0)*LAT + j], a1 = As[(m4+1)*LAT + j];
            float a2 = As[(m4+2)*LAT + j], a3 = As[(m4+3)*LAT + j];
            float4 h = *(const float4*)&sv[m4];
            acc = fmaf(h.x, a0, fmaf(h.y, a1, fmaf(h.z, a2, fmaf(h.w, a3, acc))));
        }
        __syncthreads();
        s = acc;
    }
}

// ---------------- launch ----------------
extern "C" void kernel_launch(void* const* d_in, const int* in_sizes, int n_in,
                              void* d_out, int out_size)
{
    const float* in  = (const float*)d_in[0];
    const float* ew0 = (const float*)d_in[1];
    const float* eb0 = (const float*)d_in[2];
    const float* ew1 = (const float*)d_in[3];
    const float* eb1 = (const float*)d_in[4];
    const float* ew2 = (const float*)d_in[5];
    const float* eb2 = (const float*)d_in[6];
    const float* gam = (const float*)d_in[7];
    const float* bet = (const float*)d_in[8];
    const float* Aw  = (const float*)d_in[9];
    const float* Bd  = (const float*)d_in[10];
    const float* dw0 = (const float*)d_in[11];
    const float* db0 = (const float*)d_in[12];
    const float* dw1 = (const float*)d_in[13];
    const float* db1 = (const float*)d_in[14];
    const float* dw2 = (const float*)d_in[15];
    const float* db2 = (const float*)d_in[16];
    float* out = (float*)d_out;

    u16 *a1, *a2, *z1, *we0, *we1, *we2, *wd0, *wd1, *wd2, *Aimg;
    cudaGetSymbolAddress((void**)&a1, g_a1);
    cudaGetSymbolAddress((void**)&a2, g_a2);
    cudaGetSymbolAddress((void**)&z1, g_z1);
    cudaGetSymbolAddress((void**)&we0, g_we0);
    cudaGetSymbolAddress((void**)&we1, g_we1);
    cudaGetSymbolAddress((void**)&we2, g_we2);
    cudaGetSymbolAddress((void**)&wd0, g_wd0);
    cudaGetSymbolAddress((void**)&wd1, g_wd1);
    cudaGetSymbolAddress((void**)&wd2, g_wd2);
    cudaGetSymbolAddress((void**)&Aimg, g_Aimg);

    const int SM128 = 38400;
    const int SM64  = 29184;
    const int SMSC  = 62976;

    cudaFuncSetAttribute(k_sq,    cudaFuncAttributeMaxDynamicSharedMemorySize, 65536);
    cudaFuncSetAttribute(k_bound, cudaFuncAttributeMaxDynamicSharedMemorySize, 66560);
    cudaFuncSetAttribute(k_scan<0>, cudaFuncAttributeMaxDynamicSharedMemorySize, SMSC);
    cudaFuncSetAttribute(k_scan<1>, cudaFuncAttributeMaxDynamicSharedMemorySize, SMSC);
    cudaFuncSetAttribute(k_gemm<64,128,0,0>,  cudaFuncAttributeMaxDynamicSharedMemorySize, SM128);
    cudaFuncSetAttribute(k_gemm<256,128,0,1>, cudaFuncAttributeMaxDynamicSharedMemorySize, SM128);
    cudaFuncSetAttribute(k_gemm<256,128,1,1>, cudaFuncAttributeMaxDynamicSharedMemorySize, SM128);
    cudaFuncSetAttribute(k_gemm<128,128,0,1>, cudaFuncAttributeMaxDynamicSharedMemorySize, SM128);
    cudaFuncSetAttribute(k_gemm<256,64,2,1>,  cudaFuncAttributeMaxDynamicSharedMemorySize, SM64);

    static cudaStream_t sB = nullptr;
    static cudaEvent_t evF = nullptr, evB = nullptr;
    if (!sB) {
        cudaStreamCreateWithFlags(&sB, cudaStreamNonBlocking);
        cudaEventCreateWithFlags(&evF, cudaEventDisableTiming);
        cudaEventCreateWithFlags(&evB, cudaEventDisableTiming);
    }

    cudaEventRecord(evF, 0);

    // ---- stream 0: encoder ----
    k_init<<<1, 128>>>();
    k_prepw<<<(64*256+255)/256,  256>>>(ew0, 64, 256, 128, we0);
    k_prepw<<<(256*256+255)/256, 256>>>(ew1, 256, 256, 128, we1);
    k_prepw<<<(256*128+255)/256, 256>>>(ew2, 256, 128, 128, we2);
    k_gemm<64,128,0,0><<<dim3(512,2), 256, SM128>>>(in, nullptr, IND,
        we0, eb0, a1, nullptr, 256);
    k_gemm<256,128,0,1><<<dim3(512,2), 256, SM128>>>(nullptr, a1, 256,
        we1, eb1, a2, nullptr, 256);
    k_gemm<256,128,1,1><<<dim3(512,1), 256, SM128>>>(nullptr, a2, 256,
        we2, eb2, nullptr, nullptr, 0);
    k_fin<<<1, 128>>>(gam, bet);

    // ---- stream B: A prep + MMA pass0, then A^32 chain, then dec preps ----
    cudaStreamWaitEvent(sB, evF, 0);
    k_prepw<<<(128*128+255)/256, 256, 0, sB>>>(Aw, 128, 128, 128, Aimg);
    k_scan<0><<<dim3(NCHUNK, 2), 256, SMSC, sB>>>(in, Bd);
    for (int s = 0; s < 5; s++) k_sq<<<32, 512, 65536, sB>>>(Aw, s);
    k_prepw<<<(128*256+255)/256, 256, 0, sB>>>(dw0, 128, 256, 128, wd0);
    k_prepw<<<(256*256+255)/256, 256, 0, sB>>>(dw1, 256, 256, 128, wd1);
    k_prepw<<<(256*64+255)/256,  256, 0, sB>>>(dw2, 256, 64, 64, wd2);
    cudaEventRecord(evB, sB);

    // ---- join, serial tail ----
    cudaStreamWaitEvent(0, evB, 0);
    k_bound<<<BATCH, 128, 66560>>>();
    k_scan<1><<<dim3(NCHUNK, 2), 256, SMSC>>>(in, Bd);
    k_gemm<128,128,0,1><<<dim3(512,2), 256, SM128>>>(nullptr, z1, 128,
        wd0, db0, a1, nullptr, 256);
    k_gemm<256,128,0,1><<<dim3(512,2), 256, SM128>>>(nullptr, a1, 256,
        wd1, db1, a2, nullptr, 256);
    k_gemm<256,64,2,1><<<dim3(512,1), 256, SM64>>>(nullptr, a2, 256,
        wd2, db2, nullptr, out, 64);
}

// round 15
// speedup vs baseline: 1.6119x; 1.0323x over previous
#include <cuda_runtime.h>
#include <cuda_fp16.h>
#include <cstdint>

typedef unsigned short u16;
typedef unsigned int u32;

#define BATCH 32
#define SEQ   2048
#define STATE 64
#define LAT   128
#define ENC   256
#define IND   320
#define NPOS  (BATCH*SEQ)
#define NCHUNK 64
#define CLEN   32

// ---------------- device scratch ----------------
__device__ float g_sum[LAT];
__device__ float g_sumsq[LAT];
__device__ float g_z0[BATCH*LAT];
__device__ float g_h0[BATCH*LAT];
__device__ float g_Ap0[LAT*LAT];
__device__ float g_Ap1[LAT*LAT];
__device__ float g_lend[NCHUNK*BATCH*LAT];
__device__ float g_sk[NCHUNK*BATCH*LAT];
__device__ u16 g_a1[(size_t)NPOS*ENC];
__device__ u16 g_a2[(size_t)NPOS*ENC];
__device__ u16 g_z1[(size_t)NPOS*LAT];
__device__ __align__(16) u16 g_we0[256*1*72];
__device__ __align__(16) u16 g_we1[256*4*72];
__device__ __align__(16) u16 g_we2[128*4*72];
__device__ __align__(16) u16 g_wd0[256*2*72];
__device__ __align__(16) u16 g_wd1[256*4*72];
__device__ __align__(16) u16 g_wd2[64*4*72];
__device__ __align__(16) u16 g_Aimg[128*2*72];

// ---------------- helpers ----------------
__device__ __forceinline__ u32 smem_u32(const void* p) {
    u32 a;
    asm("{ .reg .u64 t; cvta.to.shared.u64 t, %1; cvt.u32.u64 %0, t; }" : "=r"(a) : "l"(p));
    return a;
}
#define LDSM4(r, a) \
    asm volatile("ldmatrix.sync.aligned.m8n8.x4.shared.b16 {%0,%1,%2,%3}, [%4];" \
        : "=r"((r)[0]), "=r"((r)[1]), "=r"((r)[2]), "=r"((r)[3]) : "r"(a))
#define MMA(d, a, b) \
    asm volatile("mma.sync.aligned.m16n8k16.row.col.f32.f16.f16.f32 " \
        "{%0,%1,%2,%3},{%4,%5,%6,%7},{%8,%9},{%0,%1,%2,%3};" \
        : "+f"((d)[0]), "+f"((d)[1]), "+f"((d)[2]), "+f"((d)[3]) \
        : "r"((a)[0]), "r"((a)[1]), "r"((a)[2]), "r"((a)[3]), "r"((b)[0]), "r"((b)[1]))
#define CPA16(dst, src) asm volatile("cp.async.cg.shared.global [%0], [%1], 16;" :: "r"(dst), "l"(src))
#define CPA_COMMIT()  asm volatile("cp.async.commit_group;" ::: "memory")
#define CPA_WAIT0()   asm volatile("cp.async.wait_group 0;" ::: "memory")
#define CPA_WAIT1()   asm volatile("cp.async.wait_group 1;" ::: "memory")
#define CPA_FLUSH() asm volatile("cp.async.commit_group;\ncp.async.wait_group 0;" ::: "memory")

__device__ __forceinline__ u16 f2h(float v) { __half h = __float2half(v); return *(u16*)&h; }
__device__ __forceinline__ u32 pack2h(float a, float b) {
    return (u32)f2h(a) | ((u32)f2h(b) << 16);
}

// ---------------- small kernels ----------------
__global__ void k_init() {
    int t = threadIdx.x;
    if (t < LAT) { g_sum[t] = 0.f; g_sumsq[t] = 0.f; }
}

__global__ void k_sq(const float* __restrict__ Aw, int step) {
    extern __shared__ float S[];
    const float* src = (step == 0) ? Aw : ((step & 1) ? g_Ap0 : g_Ap1);
    float* dst = (step & 1) ? g_Ap1 : g_Ap0;
    int t = threadIdx.x;
    for (int i = t; i < LAT*LAT; i += 512) S[i] = src[i];
    __syncthreads();
    int base = blockIdx.x * 512 + t;
    int i = base >> 7, j = base & 127;
    float acc = 0.f;
#pragma unroll 8
    for (int k = 0; k < LAT; k++) acc = fmaf(S[i*LAT + k], S[k*LAT + j], acc);
    dst[base] = acc;
}

__global__ void k_prepw(const float* __restrict__ W, int K, int N, int NT,
                        u16* __restrict__ oh) {
    int idx = blockIdx.x * 256 + threadIdx.x;
    if (idx >= K * N) return;
    int k = idx / N, n = idx % N;
    int NCH = K >> 6;
    int nt = n / NT, nloc = n % NT, c = k >> 6, kl = k & 63;
    size_t d = ((size_t)(nt * NCH + c) * NT + nloc) * 72 + kl;
    oh[d] = f2h(W[idx]);
}

// ---------------- HMMA GEMM: fp16 1-pass, A+W double-buffered (2 CTAs/SM) ----------------
// EPI 0: bias+relu -> fp16 out; EPI 1: BN stats + z0; EPI 2: bias -> fp32 out
// ASRC 0: A fp32 (convert on load, NCH==1 only); 1: A fp16 array
template<int K, int NT, int EPI, int ASRC>
__global__ void __launch_bounds__(256, 2) k_gemm(
    const float* __restrict__ A32, const u16* __restrict__ Ax, int lda,
    const u16* __restrict__ Wx,
    const float* __restrict__ bias,
    u16* __restrict__ Ox, float* __restrict__ outF, int ldo)
{
    constexpr int KC  = 64;
    constexpr int NCH = K / KC;
    constexpr int ST  = (NCH > 1) ? 2 : 1;
    constexpr int SMA = 128 * 144;
    constexpr int SMW = NT * 144;
    constexpr int STB = SMA + SMW;          // one stage: A then W
    constexpr int SB  = ST * STB;
    constexpr int MT  = (NT == 128) ? 2 : 1;
    constexpr int WM  = (NT == 128) ? 4 : 8;

    extern __shared__ char sm[];
    u32 sb = smem_u32(sm);
    int tid = threadIdx.x, wid = tid >> 5, l = tid & 31;
    int wm = wid % WM, wn = wid / WM;
    int tile = blockIdx.x, nt = blockIdx.y, nt0 = nt * NT;
    int RW = wm * (MT * 16);

    float* sbias = (float*)(sm + SB);
    float* ssum  = (float*)(sm + SB + 512);
    float* ssq   = (float*)(sm + SB + 1024);
    if (tid < NT) sbias[tid] = bias[nt0 + tid];
    if (EPI == 1 && tid < 128) { ssum[tid] = 0.f; ssq[tid] = 0.f; }

    float acc[MT][8][4];
#pragma unroll
    for (int mt = 0; mt < MT; mt++)
#pragma unroll
        for (int n = 0; n < 8; n++)
#pragma unroll
            for (int i = 0; i < 4; i++) acc[mt][n][i] = 0.f;

    u32 aoff = (RW + (l & 15)) * 144 + (l >> 4) * 16;
    u32 boff = (wn*64 + (l & 7) + ((l >> 4) * 8)) * 144 + (((l >> 3) & 1) * 16);

    // async load of chunk c into stage s
    auto load_chunk = [&](int c, int s) {
        u32 base = sb + s * STB;
        const u16* wp = Wx + (size_t)(nt * NCH + c) * NT * 72;
#pragma unroll
        for (int i = tid; i < NT * 9; i += 256)
            CPA16(base + SMA + i*16, wp + i*8);
        if (ASRC == 1) {
#pragma unroll
            for (int i = tid; i < 1024; i += 256) {
                int row = i >> 3, seg = i & 7;
                size_t go = (size_t)(tile*128 + row) * lda + c*KC + seg*8;
                CPA16(base + row*144 + seg*16, Ax + go);
            }
        }
    };

    // prologue: chunk 0 into stage 0
    load_chunk(0, 0);
    if (ASRC == 0) {       // fp32 convert path (single chunk)
        int r = tid & 127, kh = (tid >> 7) * 32;
        const float* ap = A32 + (size_t)(tile*128 + r) * lda + kh;
#pragma unroll
        for (int j = 0; j < 4; j++) {
            float4 f0 = *(const float4*)(ap + j*8);
            float4 f1 = *(const float4*)(ap + j*8 + 4);
            float f[8] = {f0.x,f0.y,f0.z,f0.w,f1.x,f1.y,f1.z,f1.w};
            union { u16 us[8]; uint4 u; } ph;
#pragma unroll
            for (int q = 0; q < 8; q++) ph.us[q] = f2h(f[q]);
            *(uint4*)(sm + r*144 + (kh + j*8)*2) = ph.u;
        }
    }
    CPA_COMMIT();

    for (int c = 0; c < NCH; c++) {
        int s = c & (ST - 1);
        bool pre = (ST == 2) && (c + 1 < NCH);
        if (pre) { load_chunk(c + 1, (c + 1) & 1); CPA_COMMIT(); }
        if (pre) CPA_WAIT1(); else CPA_WAIT0();
        __syncthreads();

        u32 sA = sb + s * STB, sW = sA + SMA;
#pragma unroll
        for (int ks = 0; ks < 4; ks++) {
            int k2 = ks * 32;
            u32 af[MT][4], bf[4][4];
#pragma unroll
            for (int mt = 0; mt < MT; mt++) LDSM4(af[mt], sA + aoff + mt*2304 + k2);
#pragma unroll
            for (int p = 0; p < 4; p++)     LDSM4(bf[p], sW + boff + p*2304 + k2);
#pragma unroll
            for (int mt = 0; mt < MT; mt++)
#pragma unroll
                for (int p = 0; p < 4; p++) {
                    MMA(acc[mt][2*p],   af[mt], bf[p]);
                    MMA(acc[mt][2*p+1], af[mt], &bf[p][2]);
                }
        }
        __syncthreads();     // compute(s) done before stage s is reloaded next iter
    }

    int g = l >> 2, tg = l & 3;
#pragma unroll
    for (int mt = 0; mt < MT; mt++) {
        int row = tile*128 + RW + mt*16 + g;
#pragma unroll
        for (int n = 0; n < 8; n++) {
            int colL = wn*64 + n*8 + tg*2;
            float b0 = sbias[colL], b1 = sbias[colL + 1];
            float v0 = acc[mt][n][0] + b0, v1 = acc[mt][n][1] + b1;
            float v2 = acc[mt][n][2] + b0, v3 = acc[mt][n][3] + b1;
            if (EPI != 2) {
                v0 = fmaxf(v0, 0.f); v1 = fmaxf(v1, 0.f);
                v2 = fmaxf(v2, 0.f); v3 = fmaxf(v3, 0.f);
            }
            if (EPI == 1) {
                atomicAdd(&ssum[colL],     v0 + v2);
                atomicAdd(&ssq[colL],      v0*v0 + v2*v2);
                atomicAdd(&ssum[colL + 1], v1 + v3);
                atomicAdd(&ssq[colL + 1],  v1*v1 + v3*v3);
                if (((tile & 15) == 0) && g == 0 && wm == 0 && mt == 0) {
                    g_z0[(tile >> 4) * LAT + colL]     = v0;
                    g_z0[(tile >> 4) * LAT + colL + 1] = v1;
                }
            } else if (EPI == 0) {
                size_t o0 = (size_t)row * ldo + nt0 + colL;
                size_t o1 = (size_t)(row + 8) * ldo + nt0 + colL;
                *(u32*)&Ox[o0] = pack2h(v0, v1);
                *(u32*)&Ox[o1] = pack2h(v2, v3);
            } else {
                *(float2*)&outF[(size_t)row * ldo + nt0 + colL]       = make_float2(v0, v1);
                *(float2*)&outF[(size_t)(row + 8) * ldo + nt0 + colL] = make_float2(v2, v3);
            }
        }
    }
    if (EPI == 1) {
        __syncthreads();
        if (tid < 128) {
            atomicAdd(&g_sum[tid],   ssum[tid]);
            atomicAdd(&g_sumsq[tid], ssq[tid]);
        }
    }
}

// ---------------- BN finalize ----------------
__global__ void k_fin(const float* __restrict__ gamma, const float* __restrict__ beta)
{
    int j = threadIdx.x;
    float inv = 1.f / (float)NPOS;
    float m  = g_sum[j] * inv;
    float v  = g_sumsq[j] * inv - m * m;
    float rs = rsqrtf(v + 1e-5f);
    float ga = gamma[j], be = beta[j];
    for (int b = 0; b < BATCH; b++) {
        float z = g_z0[b*LAT + j];
        g_h0[b*LAT + j] = (z - m) * rs * ga + be;
    }
}

// ---------------- MMA scan with bu cp.async prefetch (unchanged from R14) ----------------
template<int PASS>
__global__ void __launch_bounds__(256) k_scan(
    const float* __restrict__ in, const float* __restrict__ Bd)
{
    constexpr int SM_A   = 0;
    constexpr int SM_H   = 36864;
    constexpr int SM_BU  = 45568;
    constexpr int BUST   = 8448;
    constexpr int SM_D   = 62464;
    extern __shared__ char sm[];
    u32 sb = smem_u32(sm);

    int tid = threadIdx.x, wid = tid >> 5, l = tid & 31;
    int chunk = blockIdx.x, b0 = blockIdx.y * 16;
    int g = l >> 2, tg = l & 3;
    int wcol = wid * 16;
    int t0 = chunk * CLEN;

    auto loadBU = [&](int t, int s) {
        u32 base = sb + SM_BU + s * BUST;
#pragma unroll
        for (int i = tid; i < 512; i += 256) {
            int row = i >> 5, seg = i & 31;
            const float* src = in + ((size_t)(b0 + row) * SEQ + t) * IND + (STATE + LAT) + seg * 4;
            CPA16(base + row * 528 + seg * 16, src);
        }
    };

    for (int i = tid; i < 2304; i += 256)
        CPA16(sb + SM_A + i*16, g_Aimg + i*8);
    loadBU(t0, 0);
    if (tid < 128) ((float*)(sm + SM_D))[tid] = fminf(fmaxf(Bd[tid], -0.95f), 0.95f);
    CPA_COMMIT();

    {
        int row = tid >> 4, cg = (tid & 15) * 8;
        u32 off = SM_H + row * 272 + cg * 2;
        if (PASS == 1) {
            const float* sp = &g_sk[(size_t)(chunk * BATCH + b0 + row) * LAT + cg];
            float4 f0 = *(const float4*)sp, f1 = *(const float4*)(sp + 4);
            *(uint4*)(sm + off) = make_uint4(pack2h(f0.x, f0.y), pack2h(f0.z, f0.w),
                                             pack2h(f1.x, f1.y), pack2h(f1.z, f1.w));
        } else {
            *(uint4*)(sm + off) = make_uint4(0, 0, 0, 0);
        }
    }
    CPA_WAIT0();
    __syncthreads();

    u32 bf[8][4];
    u32 boffb = (u32)((wcol + (l & 7) + ((l >> 4) * 8)) * 144 + (((l >> 3) & 1) * 16));
#pragma unroll
    for (int ks = 0; ks < 8; ks++)
        LDSM4(bf[ks], sb + SM_A + (ks >> 2) * 18432 + boffb + (ks & 3) * 32);

    const float* sd = (const float*)(sm + SM_D);
    float da0 = sd[wcol + tg*2],     da1 = sd[wcol + tg*2 + 1];
    float db0 = sd[wcol + 8 + tg*2], db1 = sd[wcol + 8 + tg*2 + 1];
    u32 aoff = (u32)((l & 15) * 272 + (l >> 4) * 16);
    int cur = 0, buf = 0;
    float c0[4], c1[4];

    for (int t = t0; t < t0 + CLEN; t++) {
        bool pre = (t + 1 < t0 + CLEN);
        if (pre) { loadBU(t + 1, buf ^ 1); CPA_COMMIT(); }
        if (pre) CPA_WAIT1(); else CPA_WAIT0();
        __syncthreads();

        {
            const char* bub = sm + SM_BU + buf * BUST;
            float2 a0 = *(float2*)(bub + g * 528 + (wcol + tg*2) * 4);
            float2 a1 = *(float2*)(bub + (g + 8) * 528 + (wcol + tg*2) * 4);
            float2 a2 = *(float2*)(bub + g * 528 + (wcol + 8 + tg*2) * 4);
            float2 a3 = *(float2*)(bub + (g + 8) * 528 + (wcol + 8 + tg*2) * 4);
            c0[0] = a0.x * da0; c0[1] = a0.y * da1; c0[2] = a1.x * da0; c0[3] = a1.y * da1;
            c1[0] = a2.x * db0; c1[1] = a2.y * db1; c1[2] = a3.x * db0; c1[3] = a3.y * db1;
        }

        u32 hbase = sb + SM_H + cur * 4352;
#pragma unroll
        for (int ks = 0; ks < 8; ks++) {
            u32 af[4];
            LDSM4(af, hbase + aoff + ks * 32);
            MMA(c0, af, bf[ks]);
            MMA(c1, af, &bf[ks][2]);
        }

        int hno = SM_H + (cur ^ 1) * 4352;
        u32 p00 = pack2h(c0[0], c0[1]), p01 = pack2h(c0[2], c0[3]);
        u32 p10 = pack2h(c1[0], c1[1]), p11 = pack2h(c1[2], c1[3]);
        *(u32*)(sm + hno + g * 272 + (wcol + tg*2) * 2)           = p00;
        *(u32*)(sm + hno + (g + 8) * 272 + (wcol + tg*2) * 2)     = p01;
        *(u32*)(sm + hno + g * 272 + (wcol + 8 + tg*2) * 2)       = p10;
        *(u32*)(sm + hno + (g + 8) * 272 + (wcol + 8 + tg*2) * 2) = p11;
        if (PASS == 1) {
            size_t r0 = ((size_t)(b0 + g) * SEQ + t) * LAT;
            size_t r1 = ((size_t)(b0 + g + 8) * SEQ + t) * LAT;
            *(u32*)&g_z1[r0 + wcol + tg*2]     = p00;
            *(u32*)&g_z1[r1 + wcol + tg*2]     = p01;
            *(u32*)&g_z1[r0 + wcol + 8 + tg*2] = p10;
            *(u32*)&g_z1[r1 + wcol + 8 + tg*2] = p11;
        }
        __syncthreads();
        cur ^= 1; buf ^= 1;
    }

    if (PASS == 0) {
        size_t r0 = (size_t)(chunk * BATCH + b0 + g) * LAT;
        size_t r1 = (size_t)(chunk * BATCH + b0 + g + 8) * LAT;
        *(float2*)&g_lend[r0 + wcol + tg*2]     = make_float2(c0[0], c0[1]);
        *(float2*)&g_lend[r1 + wcol + tg*2]     = make_float2(c0[2], c0[3]);
        *(float2*)&g_lend[r0 + wcol + 8 + tg*2] = make_float2(c1[0], c1[1]);
        *(float2*)&g_lend[r1 + wcol + 8 + tg*2] = make_float2(c1[2], c1[3]);
    }
}

// ---------------- boundary scan via A^32 ----------------
__global__ void __launch_bounds__(128) k_bound()
{
    extern __shared__ float smf[];
    float* As = smf;
    float* sv = smf + LAT * LAT;
    int j = threadIdx.x;
    int b = blockIdx.x;
    for (int idx = j; idx < LAT * LAT; idx += 128) As[idx] = g_Ap0[idx];
    float s = g_h0[b * LAT + j];
    for (int k = 0; k < NCHUNK; k++) {
        g_sk[(k * BATCH + b) * LAT + j] = s;
        sv[j] = s;
        __syncthreads();
        float acc = g_lend[(k * BATCH + b) * LAT + j];
#pragma unroll 8
        for (int m4 = 0; m4 < LAT; m4 += 4) {
            float a0 = As[(m4+0)*LAT + j], a1 = As[(m4+1)*LAT + j];
            float a2 = As[(m4+2)*LAT + j], a3 = As[(m4+3)*LAT + j];
            float4 h = *(const float4*)&sv[m4];
            acc = fmaf(h.x, a0, fmaf(h.y, a1, fmaf(h.z, a2, fmaf(h.w, a3, acc))));
        }
        __syncthreads();
        s = acc;
    }
}

// ---------------- launch ----------------
extern "C" void kernel_launch(void* const* d_in, const int* in_sizes, int n_in,
                              void* d_out, int out_size)
{
    const float* in  = (const float*)d_in[0];
    const float* ew0 = (const float*)d_in[1];
    const float* eb0 = (const float*)d_in[2];
    const float* ew1 = (const float*)d_in[3];
    const float* eb1 = (const float*)d_in[4];
    const float* ew2 = (const float*)d_in[5];
    const float* eb2 = (const float*)d_in[6];
    const float* gam = (const float*)d_in[7];
    const float* bet = (const float*)d_in[8];
    const float* Aw  = (const float*)d_in[9];
    const float* Bd  = (const float*)d_in[10];
    const float* dw0 = (const float*)d_in[11];
    const float* db0 = (const float*)d_in[12];
    const float* dw1 = (const float*)d_in[13];
    const float* db1 = (const float*)d_in[14];
    const float* dw2 = (const float*)d_in[15];
    const float* db2 = (const float*)d_in[16];
    float* out = (float*)d_out;

    u16 *a1, *a2, *z1, *we0, *we1, *we2, *wd0, *wd1, *wd2, *Aimg;
    cudaGetSymbolAddress((void**)&a1, g_a1);
    cudaGetSymbolAddress((void**)&a2, g_a2);
    cudaGetSymbolAddress((void**)&z1, g_z1);
    cudaGetSymbolAddress((void**)&we0, g_we0);
    cudaGetSymbolAddress((void**)&we1, g_we1);
    cudaGetSymbolAddress((void**)&we2, g_we2);
    cudaGetSymbolAddress((void**)&wd0, g_wd0);
    cudaGetSymbolAddress((void**)&wd1, g_wd1);
    cudaGetSymbolAddress((void**)&wd2, g_wd2);
    cudaGetSymbolAddress((void**)&Aimg, g_Aimg);

    // smem: NCH==1 NT=128: 1*(18432+18432)+1536 = 38400
    //       NCH>1  NT=128: 2*(18432+18432)+1536 = 75264  (x2 CTAs = 150528 <= 233472)
    //       NCH>1  NT=64:  2*(18432+9216) +1536 = 56832
    const int SM_L0   = 38400;
    const int SM_P128 = 75264;
    const int SM_P64  = 56832;
    const int SMSC    = 62976;

    cudaFuncSetAttribute(k_sq,    cudaFuncAttributeMaxDynamicSharedMemorySize, 65536);
    cudaFuncSetAttribute(k_bound, cudaFuncAttributeMaxDynamicSharedMemorySize, 66560);
    cudaFuncSetAttribute(k_scan<0>, cudaFuncAttributeMaxDynamicSharedMemorySize, SMSC);
    cudaFuncSetAttribute(k_scan<1>, cudaFuncAttributeMaxDynamicSharedMemorySize, SMSC);
    cudaFuncSetAttribute(k_gemm<64,128,0,0>,  cudaFuncAttributeMaxDynamicSharedMemorySize, SM_L0);
    cudaFuncSetAttribute(k_gemm<256,128,0,1>, cudaFuncAttributeMaxDynamicSharedMemorySize, SM_P128);
    cudaFuncSetAttribute(k_gemm<256,128,1,1>, cudaFuncAttributeMaxDynamicSharedMemorySize, SM_P128);
    cudaFuncSetAttribute(k_gemm<128,128,0,1>, cudaFuncAttributeMaxDynamicSharedMemorySize, SM_P128);
    cudaFuncSetAttribute(k_gemm<256,64,2,1>,  cudaFuncAttributeMaxDynamicSharedMemorySize, SM_P64);

    static cudaStream_t sB = nullptr;
    static cudaEvent_t evF = nullptr, evB = nullptr;
    if (!sB) {
        cudaStreamCreateWithFlags(&sB, cudaStreamNonBlocking);
        cudaEventCreateWithFlags(&evF, cudaEventDisableTiming);
        cudaEventCreateWithFlags(&evB, cudaEventDisableTiming);
    }

    cudaEventRecord(evF, 0);

    // ---- stream 0: encoder ----
    k_init<<<1, 128>>>();
    k_prepw<<<(64*256+255)/256,  256>>>(ew0, 64, 256, 128, we0);
    k_prepw<<<(256*256+255)/256, 256>>>(ew1, 256, 256, 128, we1);
    k_prepw<<<(256*128+255)/256, 256>>>(ew2, 256, 128, 128, we2);
    k_gemm<64,128,0,0><<<dim3(512,2), 256, SM_L0>>>(in, nullptr, IND,
        we0, eb0, a1, nullptr, 256);
    k_gemm<256,128,0,1><<<dim3(512,2), 256, SM_P128>>>(nullptr, a1, 256,
        we1, eb1, a2, nullptr, 256);
    k_gemm<256,128,1,1><<<dim3(512,1), 256, SM_P128>>>(nullptr, a2, 256,
        we2, eb2, nullptr, nullptr, 0);
    k_fin<<<1, 128>>>(gam, bet);

    // ---- stream B: A prep + MMA pass0, then A^32 chain, then dec preps ----
    cudaStreamWaitEvent(sB, evF, 0);
    k_prepw<<<(128*128+255)/256, 256, 0, sB>>>(Aw, 128, 128, 128, Aimg);
    k_scan<0><<<dim3(NCHUNK, 2), 256, SMSC, sB>>>(in, Bd);
    for (int s = 0; s < 5; s++) k_sq<<<32, 512, 65536, sB>>>(Aw, s);
    k_prepw<<<(128*256+255)/256, 256, 0, sB>>>(dw0, 128, 256, 128, wd0);
    k_prepw<<<(256*256+255)/256, 256, 0, sB>>>(dw1, 256, 256, 128, wd1);
    k_prepw<<<(256*64+255)/256,  256, 0, sB>>>(dw2, 256, 64, 64, wd2);
    cudaEventRecord(evB, sB);

    // ---- join, serial tail ----
    cudaStreamWaitEvent(0, evB, 0);
    k_bound<<<BATCH, 128, 66560>>>();
    k_scan<1><<<dim3(NCHUNK, 2), 256, SMSC>>>(in, Bd);
    k_gemm<128,128,0,1><<<dim3(512,2), 256, SM_P128>>>(nullptr, z1, 128,
        wd0, db0, a1, nullptr, 256);
    k_gemm<256,128,0,1><<<dim3(512,2), 256, SM_P128>>>(nullptr, a1, 256,
        wd1, db1, a2, nullptr, 256);
    k_gemm<256,64,2,1><<<dim3(512,1), 256, SM_P64>>>(nullptr, a2, 256,
        wd2, db2, nullptr, out, 64);
}

// round 16
// speedup vs baseline: 1.7205x; 1.0673x over previous
#include <cuda_runtime.h>
#include <cuda_fp16.h>
#include <cstdint>

typedef unsigned short u16;
typedef unsigned int u32;

#define BATCH 32
#define SEQ   2048
#define STATE 64
#define LAT   128
#define ENC   256
#define IND   320
#define NPOS  (BATCH*SEQ)
#define NCHUNK 64
#define CLEN   32

// ---------------- device scratch ----------------
__device__ float g_sum[LAT];
__device__ float g_sumsq[LAT];
__device__ float g_z0[BATCH*LAT];
__device__ float g_h0[BATCH*LAT];
__device__ float g_Ap0[LAT*LAT];
__device__ float g_Ap1[LAT*LAT];
__device__ float g_lend[NCHUNK*BATCH*LAT];
__device__ float g_sk[NCHUNK*BATCH*LAT];
__device__ u16 g_a1[(size_t)NPOS*ENC];
__device__ u16 g_a2[(size_t)NPOS*ENC];
__device__ u16 g_z1[(size_t)NPOS*LAT];
__device__ __align__(16) u16 g_we0[256*1*72];
__device__ __align__(16) u16 g_we1[256*4*72];
__device__ __align__(16) u16 g_we2[128*4*72];
__device__ __align__(16) u16 g_wd0[256*2*72];
__device__ __align__(16) u16 g_wd1[256*4*72];
__device__ __align__(16) u16 g_wd2[64*4*72];
__device__ __align__(16) u16 g_Aimg[128*2*72];

// ---------------- helpers ----------------
__device__ __forceinline__ u32 smem_u32(const void* p) {
    u32 a;
    asm("{ .reg .u64 t; cvta.to.shared.u64 t, %1; cvt.u32.u64 %0, t; }" : "=r"(a) : "l"(p));
    return a;
}
#define LDSM4(r, a) \
    asm volatile("ldmatrix.sync.aligned.m8n8.x4.shared.b16 {%0,%1,%2,%3}, [%4];" \
        : "=r"((r)[0]), "=r"((r)[1]), "=r"((r)[2]), "=r"((r)[3]) : "r"(a))
#define MMA(d, a, b) \
    asm volatile("mma.sync.aligned.m16n8k16.row.col.f32.f16.f16.f32 " \
        "{%0,%1,%2,%3},{%4,%5,%6,%7},{%8,%9},{%0,%1,%2,%3};" \
        : "+f"((d)[0]), "+f"((d)[1]), "+f"((d)[2]), "+f"((d)[3]) \
        : "r"((a)[0]), "r"((a)[1]), "r"((a)[2]), "r"((a)[3]), "r"((b)[0]), "r"((b)[1]))
#define CPA16(dst, src) asm volatile("cp.async.cg.shared.global [%0], [%1], 16;" :: "r"(dst), "l"(src))
#define CPA_COMMIT()  asm volatile("cp.async.commit_group;" ::: "memory")
#define CPA_WAIT0()   asm volatile("cp.async.wait_group 0;" ::: "memory")
#define CPA_WAIT1()   asm volatile("cp.async.wait_group 1;" ::: "memory")

__device__ __forceinline__ u16 f2h(float v) { __half h = __float2half(v); return *(u16*)&h; }
__device__ __forceinline__ u32 pack2h(float a, float b) {
    return (u32)f2h(a) | ((u32)f2h(b) << 16);
}

// ---------------- fused prep: all weight images + A image + stat init ----------------
__device__ __forceinline__ void prep_one(const float* W, int K, int N, int NT,
                                         u16* oh, int idx) {
    if (idx >= K * N) return;
    int k = idx / N, n = idx % N;
    int NCH = K >> 6;
    int nt = n / NT, nloc = n % NT, c = k >> 6, kl = k & 63;
    size_t d = ((size_t)(nt * NCH + c) * NT + nloc) * 72 + kl;
    oh[d] = f2h(W[idx]);
}

// block ranges: we0[0,64) we1[64,320) we2[320,448) Aimg[448,512)
//               wd0[512,640) wd1[640,896) wd2[896,960)
__global__ void k_prep_all(const float* __restrict__ ew0, const float* __restrict__ ew1,
                           const float* __restrict__ ew2, const float* __restrict__ Aw,
                           const float* __restrict__ dw0, const float* __restrict__ dw1,
                           const float* __restrict__ dw2)
{
    int b = blockIdx.x, t = threadIdx.x;
    if (b == 0 && t < LAT) { g_sum[t] = 0.f; g_sumsq[t] = 0.f; }
    if (b < 64)        prep_one(ew0, 64, 256, 128, g_we0, b * 256 + t);
    else if (b < 320)  prep_one(ew1, 256, 256, 128, g_we1, (b - 64) * 256 + t);
    else if (b < 448)  prep_one(ew2, 256, 128, 128, g_we2, (b - 320) * 256 + t);
    else if (b < 512)  prep_one(Aw, 128, 128, 128, g_Aimg, (b - 448) * 256 + t);
    else if (b < 640)  prep_one(dw0, 128, 256, 128, g_wd0, (b - 512) * 256 + t);
    else if (b < 896)  prep_one(dw1, 256, 256, 128, g_wd1, (b - 640) * 256 + t);
    else               prep_one(dw2, 256, 64, 64, g_wd2, (b - 896) * 256 + t);
}

// ---------------- repeated squaring ----------------
__global__ void k_sq(const float* __restrict__ Aw, int step) {
    extern __shared__ float S[];
    const float* src = (step == 0) ? Aw : ((step & 1) ? g_Ap0 : g_Ap1);
    float* dst = (step & 1) ? g_Ap1 : g_Ap0;
    int t = threadIdx.x;
    for (int i = t; i < LAT*LAT; i += 512) S[i] = src[i];
    __syncthreads();
    int base = blockIdx.x * 512 + t;
    int i = base >> 7, j = base & 127;
    float acc = 0.f;
#pragma unroll 8
    for (int k = 0; k < LAT; k++) acc = fmaf(S[i*LAT + k], S[k*LAT + j], acc);
    dst[base] = acc;
}

// ---------------- HMMA GEMM: fp16 1-pass, A+W double-buffered ----------------
template<int K, int NT, int EPI, int ASRC>
__global__ void __launch_bounds__(256, 2) k_gemm(
    const float* __restrict__ A32, const u16* __restrict__ Ax, int lda,
    const u16* __restrict__ Wx,
    const float* __restrict__ bias,
    u16* __restrict__ Ox, float* __restrict__ outF, int ldo)
{
    constexpr int KC  = 64;
    constexpr int NCH = K / KC;
    constexpr int ST  = (NCH > 1) ? 2 : 1;
    constexpr int SMA = 128 * 144;
    constexpr int SMW = NT * 144;
    constexpr int STB = SMA + SMW;
    constexpr int SB  = ST * STB;
    constexpr int MT  = (NT == 128) ? 2 : 1;
    constexpr int WM  = (NT == 128) ? 4 : 8;

    extern __shared__ char sm[];
    u32 sb = smem_u32(sm);
    int tid = threadIdx.x, wid = tid >> 5, l = tid & 31;
    int wm = wid % WM, wn = wid / WM;
    int tile = blockIdx.x, nt = blockIdx.y, nt0 = nt * NT;
    int RW = wm * (MT * 16);

    float* sbias = (float*)(sm + SB);
    float* ssum  = (float*)(sm + SB + 512);
    float* ssq   = (float*)(sm + SB + 1024);
    if (tid < NT) sbias[tid] = bias[nt0 + tid];
    if (EPI == 1 && tid < 128) { ssum[tid] = 0.f; ssq[tid] = 0.f; }

    float acc[MT][8][4];
#pragma unroll
    for (int mt = 0; mt < MT; mt++)
#pragma unroll
        for (int n = 0; n < 8; n++)
#pragma unroll
            for (int i = 0; i < 4; i++) acc[mt][n][i] = 0.f;

    u32 aoff = (RW + (l & 15)) * 144 + (l >> 4) * 16;
    u32 boff = (wn*64 + (l & 7) + ((l >> 4) * 8)) * 144 + (((l >> 3) & 1) * 16);

    auto load_chunk = [&](int c, int s) {
        u32 base = sb + s * STB;
        const u16* wp = Wx + (size_t)(nt * NCH + c) * NT * 72;
#pragma unroll
        for (int i = tid; i < NT * 9; i += 256)
            CPA16(base + SMA + i*16, wp + i*8);
        if (ASRC == 1) {
#pragma unroll
            for (int i = tid; i < 1024; i += 256) {
                int row = i >> 3, seg = i & 7;
                size_t go = (size_t)(tile*128 + row) * lda + c*KC + seg*8;
                CPA16(base + row*144 + seg*16, Ax + go);
            }
        }
    };

    load_chunk(0, 0);
    if (ASRC == 0) {
        int r = tid & 127, kh = (tid >> 7) * 32;
        const float* ap = A32 + (size_t)(tile*128 + r) * lda + kh;
#pragma unroll
        for (int j = 0; j < 4; j++) {
            float4 f0 = *(const float4*)(ap + j*8);
            float4 f1 = *(const float4*)(ap + j*8 + 4);
            float f[8] = {f0.x,f0.y,f0.z,f0.w,f1.x,f1.y,f1.z,f1.w};
            union { u16 us[8]; uint4 u; } ph;
#pragma unroll
            for (int q = 0; q < 8; q++) ph.us[q] = f2h(f[q]);
            *(uint4*)(sm + r*144 + (kh + j*8)*2) = ph.u;
        }
    }
    CPA_COMMIT();

    for (int c = 0; c < NCH; c++) {
        int s = c & (ST - 1);
        bool pre = (ST == 2) && (c + 1 < NCH);
        if (pre) { load_chunk(c + 1, (c + 1) & 1); CPA_COMMIT(); }
        if (pre) CPA_WAIT1(); else CPA_WAIT0();
        __syncthreads();

        u32 sA = sb + s * STB, sW = sA + SMA;
#pragma unroll
        for (int ks = 0; ks < 4; ks++) {
            int k2 = ks * 32;
            u32 af[MT][4], bf[4][4];
#pragma unroll
            for (int mt = 0; mt < MT; mt++) LDSM4(af[mt], sA + aoff + mt*2304 + k2);
#pragma unroll
            for (int p = 0; p < 4; p++)     LDSM4(bf[p], sW + boff + p*2304 + k2);
#pragma unroll
            for (int mt = 0; mt < MT; mt++)
#pragma unroll
                for (int p = 0; p < 4; p++) {
                    MMA(acc[mt][2*p],   af[mt], bf[p]);
                    MMA(acc[mt][2*p+1], af[mt], &bf[p][2]);
                }
        }
        __syncthreads();
    }

    int g = l >> 2, tg = l & 3;
#pragma unroll
    for (int mt = 0; mt < MT; mt++) {
        int row = tile*128 + RW + mt*16 + g;
#pragma unroll
        for (int n = 0; n < 8; n++) {
            int colL = wn*64 + n*8 + tg*2;
            float b0 = sbias[colL], b1 = sbias[colL + 1];
            float v0 = acc[mt][n][0] + b0, v1 = acc[mt][n][1] + b1;
            float v2 = acc[mt][n][2] + b0, v3 = acc[mt][n][3] + b1;
            if (EPI != 2) {
                v0 = fmaxf(v0, 0.f); v1 = fmaxf(v1, 0.f);
                v2 = fmaxf(v2, 0.f); v3 = fmaxf(v3, 0.f);
            }
            if (EPI == 1) {
                atomicAdd(&ssum[colL],     v0 + v2);
                atomicAdd(&ssq[colL],      v0*v0 + v2*v2);
                atomicAdd(&ssum[colL + 1], v1 + v3);
                atomicAdd(&ssq[colL + 1],  v1*v1 + v3*v3);
                if (((tile & 15) == 0) && g == 0 && wm == 0 && mt == 0) {
                    g_z0[(tile >> 4) * LAT + colL]     = v0;
                    g_z0[(tile >> 4) * LAT + colL + 1] = v1;
                }
            } else if (EPI == 0) {
                size_t o0 = (size_t)row * ldo + nt0 + colL;
                size_t o1 = (size_t)(row + 8) * ldo + nt0 + colL;
                *(u32*)&Ox[o0] = pack2h(v0, v1);
                *(u32*)&Ox[o1] = pack2h(v2, v3);
            } else {
                *(float2*)&outF[(size_t)row * ldo + nt0 + colL]       = make_float2(v0, v1);
                *(float2*)&outF[(size_t)(row + 8) * ldo + nt0 + colL] = make_float2(v2, v3);
            }
        }
    }
    if (EPI == 1) {
        __syncthreads();
        if (tid < 128) {
            atomicAdd(&g_sum[tid],   ssum[tid]);
            atomicAdd(&g_sumsq[tid], ssq[tid]);
        }
    }
}

// ---------------- MMA scan with bu cp.async prefetch ----------------
template<int PASS>
__global__ void __launch_bounds__(256) k_scan(
    const float* __restrict__ in, const float* __restrict__ Bd)
{
    constexpr int SM_A   = 0;
    constexpr int SM_H   = 36864;
    constexpr int SM_BU  = 45568;
    constexpr int BUST   = 8448;
    constexpr int SM_D   = 62464;
    extern __shared__ char sm[];
    u32 sb = smem_u32(sm);

    int tid = threadIdx.x, wid = tid >> 5, l = tid & 31;
    int chunk = blockIdx.x, b0 = blockIdx.y * 16;
    int g = l >> 2, tg = l & 3;
    int wcol = wid * 16;
    int t0 = chunk * CLEN;

    auto loadBU = [&](int t, int s) {
        u32 base = sb + SM_BU + s * BUST;
#pragma unroll
        for (int i = tid; i < 512; i += 256) {
            int row = i >> 5, seg = i & 31;
            const float* src = in + ((size_t)(b0 + row) * SEQ + t) * IND + (STATE + LAT) + seg * 4;
            CPA16(base + row * 528 + seg * 16, src);
        }
    };

    for (int i = tid; i < 2304; i += 256)
        CPA16(sb + SM_A + i*16, g_Aimg + i*8);
    loadBU(t0, 0);
    if (tid < 128) ((float*)(sm + SM_D))[tid] = fminf(fmaxf(Bd[tid], -0.95f), 0.95f);
    CPA_COMMIT();

    {
        int row = tid >> 4, cg = (tid & 15) * 8;
        u32 off = SM_H + row * 272 + cg * 2;
        if (PASS == 1) {
            const float* sp = &g_sk[(size_t)(chunk * BATCH + b0 + row) * LAT + cg];
            float4 f0 = *(const float4*)sp, f1 = *(const float4*)(sp + 4);
            *(uint4*)(sm + off) = make_uint4(pack2h(f0.x, f0.y), pack2h(f0.z, f0.w),
                                             pack2h(f1.x, f1.y), pack2h(f1.z, f1.w));
        } else {
            *(uint4*)(sm + off) = make_uint4(0, 0, 0, 0);
        }
    }
    CPA_WAIT0();
    __syncthreads();

    u32 bf[8][4];
    u32 boffb = (u32)((wcol + (l & 7) + ((l >> 4) * 8)) * 144 + (((l >> 3) & 1) * 16));
#pragma unroll
    for (int ks = 0; ks < 8; ks++)
        LDSM4(bf[ks], sb + SM_A + (ks >> 2) * 18432 + boffb + (ks & 3) * 32);

    const float* sd = (const float*)(sm + SM_D);
    float da0 = sd[wcol + tg*2],     da1 = sd[wcol + tg*2 + 1];
    float db0 = sd[wcol + 8 + tg*2], db1 = sd[wcol + 8 + tg*2 + 1];
    u32 aoff = (u32)((l & 15) * 272 + (l >> 4) * 16);
    int cur = 0, buf = 0;
    float c0[4], c1[4];

    for (int t = t0; t < t0 + CLEN; t++) {
        bool pre = (t + 1 < t0 + CLEN);
        if (pre) { loadBU(t + 1, buf ^ 1); CPA_COMMIT(); }
        if (pre) CPA_WAIT1(); else CPA_WAIT0();
        __syncthreads();

        {
            const char* bub = sm + SM_BU + buf * BUST;
            float2 a0 = *(float2*)(bub + g * 528 + (wcol + tg*2) * 4);
            float2 a1 = *(float2*)(bub + (g + 8) * 528 + (wcol + tg*2) * 4);
            float2 a2 = *(float2*)(bub + g * 528 + (wcol + 8 + tg*2) * 4);
            float2 a3 = *(float2*)(bub + (g + 8) * 528 + (wcol + 8 + tg*2) * 4);
            c0[0] = a0.x * da0; c0[1] = a0.y * da1; c0[2] = a1.x * da0; c0[3] = a1.y * da1;
            c1[0] = a2.x * db0; c1[1] = a2.y * db1; c1[2] = a3.x * db0; c1[3] = a3.y * db1;
        }

        u32 hbase = sb + SM_H + cur * 4352;
#pragma unroll
        for (int ks = 0; ks < 8; ks++) {
            u32 af[4];
            LDSM4(af, hbase + aoff + ks * 32);
            MMA(c0, af, bf[ks]);
            MMA(c1, af, &bf[ks][2]);
        }

        int hno = SM_H + (cur ^ 1) * 4352;
        u32 p00 = pack2h(c0[0], c0[1]), p01 = pack2h(c0[2], c0[3]);
        u32 p10 = pack2h(c1[0], c1[1]), p11 = pack2h(c1[2], c1[3]);
        *(u32*)(sm + hno + g * 272 + (wcol + tg*2) * 2)           = p00;
        *(u32*)(sm + hno + (g + 8) * 272 + (wcol + tg*2) * 2)     = p01;
        *(u32*)(sm + hno + g * 272 + (wcol + 8 + tg*2) * 2)       = p10;
        *(u32*)(sm + hno + (g + 8) * 272 + (wcol + 8 + tg*2) * 2) = p11;
        if (PASS == 1) {
            size_t r0 = ((size_t)(b0 + g) * SEQ + t) * LAT;
            size_t r1 = ((size_t)(b0 + g + 8) * SEQ + t) * LAT;
            *(u32*)&g_z1[r0 + wcol + tg*2]     = p00;
            *(u32*)&g_z1[r1 + wcol + tg*2]     = p01;
            *(u32*)&g_z1[r0 + wcol + 8 + tg*2] = p10;
            *(u32*)&g_z1[r1 + wcol + 8 + tg*2] = p11;
        }
        __syncthreads();
        cur ^= 1; buf ^= 1;
    }

    if (PASS == 0) {
        size_t r0 = (size_t)(chunk * BATCH + b0 + g) * LAT;
        size_t r1 = (size_t)(chunk * BATCH + b0 + g + 8) * LAT;
        *(float2*)&g_lend[r0 + wcol + tg*2]     = make_float2(c0[0], c0[1]);
        *(float2*)&g_lend[r1 + wcol + tg*2]     = make_float2(c0[2], c0[3]);
        *(float2*)&g_lend[r0 + wcol + 8 + tg*2] = make_float2(c1[0], c1[1]);
        *(float2*)&g_lend[r1 + wcol + 8 + tg*2] = make_float2(c1[2], c1[3]);
    }
}

// ---------------- boundary scan (BN finalize fused) ----------------
__global__ void __launch_bounds__(128) k_bound(const float* __restrict__ gamma,
                                               const float* __restrict__ beta)
{
    extern __shared__ float smf[];
    float* As = smf;
    float* sv = smf + LAT * LAT;
    int j = threadIdx.x;
    int b = blockIdx.x;

    // fused BN finalize for this batch row
    float inv = 1.f / (float)NPOS;
    float m  = g_sum[j] * inv;
    float v  = g_sumsq[j] * inv - m * m;
    float rs = rsqrtf(v + 1e-5f);
    float s = (g_z0[b * LAT + j] - m) * rs * gamma[j] + beta[j];

    for (int idx = j; idx < LAT * LAT; idx += 128) As[idx] = g_Ap0[idx];
    __syncthreads();
    for (int k = 0; k < NCHUNK; k++) {
        g_sk[(k * BATCH + b) * LAT + j] = s;
        sv[j] = s;
        __syncthreads();
        float acc = g_lend[(k * BATCH + b) * LAT + j];
#pragma unroll 8
        for (int m4 = 0; m4 < LAT; m4 += 4) {
            float a0 = As[(m4+0)*LAT + j], a1 = As[(m4+1)*LAT + j];
            float a2 = As[(m4+2)*LAT + j], a3 = As[(m4+3)*LAT + j];
            float4 h = *(const float4*)&sv[m4];
            acc = fmaf(h.x, a0, fmaf(h.y, a1, fmaf(h.z, a2, fmaf(h.w, a3, acc))));
        }
        __syncthreads();
        s = acc;
    }
}

// ---------------- launch ----------------
extern "C" void kernel_launch(void* const* d_in, const int* in_sizes, int n_in,
                              void* d_out, int out_size)
{
    const float* in  = (const float*)d_in[0];
    const float* ew0 = (const float*)d_in[1];
    const float* eb0 = (const float*)d_in[2];
    const float* ew1 = (const float*)d_in[3];
    const float* eb1 = (const float*)d_in[4];
    const float* ew2 = (const float*)d_in[5];
    const float* eb2 = (const float*)d_in[6];
    const float* gam = (const float*)d_in[7];
    const float* bet = (const float*)d_in[8];
    const float* Aw  = (const float*)d_in[9];
    const float* Bd  = (const float*)d_in[10];
    const float* dw0 = (const float*)d_in[11];
    const float* db0 = (const float*)d_in[12];
    const float* dw1 = (const float*)d_in[13];
    const float* db1 = (const float*)d_in[14];
    const float* dw2 = (const float*)d_in[15];
    const float* db2 = (const float*)d_in[16];
    float* out = (float*)d_out;

    u16 *a1, *a2, *z1, *we0, *we1, *we2, *wd0, *wd1, *wd2;
    cudaGetSymbolAddress((void**)&a1, g_a1);
    cudaGetSymbolAddress((void**)&a2, g_a2);
    cudaGetSymbolAddress((void**)&z1, g_z1);
    cudaGetSymbolAddress((void**)&we0, g_we0);
    cudaGetSymbolAddress((void**)&we1, g_we1);
    cudaGetSymbolAddress((void**)&we2, g_we2);
    cudaGetSymbolAddress((void**)&wd0, g_wd0);
    cudaGetSymbolAddress((void**)&wd1, g_wd1);
    cudaGetSymbolAddress((void**)&wd2, g_wd2);

    const int SM_L0   = 38400;
    const int SM_P128 = 75264;
    const int SM_P64  = 56832;
    const int SMSC    = 62976;

    cudaFuncSetAttribute(k_sq,    cudaFuncAttributeMaxDynamicSharedMemorySize, 65536);
    cudaFuncSetAttribute(k_bound, cudaFuncAttributeMaxDynamicSharedMemorySize, 66560);
    cudaFuncSetAttribute(k_scan<0>, cudaFuncAttributeMaxDynamicSharedMemorySize, SMSC);
    cudaFuncSetAttribute(k_scan<1>, cudaFuncAttributeMaxDynamicSharedMemorySize, SMSC);
    cudaFuncSetAttribute(k_gemm<64,128,0,0>,  cudaFuncAttributeMaxDynamicSharedMemorySize, SM_L0);
    cudaFuncSetAttribute(k_gemm<256,128,0,1>, cudaFuncAttributeMaxDynamicSharedMemorySize, SM_P128);
    cudaFuncSetAttribute(k_gemm<256,128,1,1>, cudaFuncAttributeMaxDynamicSharedMemorySize, SM_P128);
    cudaFuncSetAttribute(k_gemm<128,128,0,1>, cudaFuncAttributeMaxDynamicSharedMemorySize, SM_P128);
    cudaFuncSetAttribute(k_gemm<256,64,2,1>,  cudaFuncAttributeMaxDynamicSharedMemorySize, SM_P64);

    static cudaStream_t sB = nullptr;
    static cudaEvent_t evP = nullptr, evB = nullptr;
    if (!sB) {
        cudaStreamCreateWithFlags(&sB, cudaStreamNonBlocking);
        cudaEventCreateWithFlags(&evP, cudaEventDisableTiming);
        cudaEventCreateWithFlags(&evB, cudaEventDisableTiming);
    }

    // ---- single fused prep (all weights + A image + stat init) ----
    k_prep_all<<<960, 256>>>(ew0, ew1, ew2, Aw, dw0, dw1, dw2);
    cudaEventRecord(evP, 0);

    // ---- stream 0: encoder ----
    k_gemm<64,128,0,0><<<dim3(512,2), 256, SM_L0>>>(in, nullptr, IND,
        we0, eb0, a1, nullptr, 256);
    k_gemm<256,128,0,1><<<dim3(512,2), 256, SM_P128>>>(nullptr, a1, 256,
        we1, eb1, a2, nullptr, 256);
    k_gemm<256,128,1,1><<<dim3(512,1), 256, SM_P128>>>(nullptr, a2, 256,
        we2, eb2, nullptr, nullptr, 0);

    // ---- stream B: pass0 + A^32 chain ----
    cudaStreamWaitEvent(sB, evP, 0);
    k_scan<0><<<dim3(NCHUNK, 2), 256, SMSC, sB>>>(in, Bd);
    for (int s = 0; s < 5; s++) k_sq<<<32, 512, 65536, sB>>>(Aw, s);
    cudaEventRecord(evB, sB);

    // ---- join, serial tail ----
    cudaStreamWaitEvent(0, evB, 0);
    k_bound<<<BATCH, 128, 66560>>>(gam, bet);
    k_scan<1><<<dim3(NCHUNK, 2), 256, SMSC>>>(in, Bd);
    k_gemm<128,128,0,1><<<dim3(512,2), 256, SM_P128>>>(nullptr, z1, 128,
        wd0, db0, a1, nullptr, 256);
    k_gemm<256,128,0,1><<<dim3(512,2), 256, SM_P128>>>(nullptr, a1, 256,
        wd1, db1, a2, nullptr, 256);
    k_gemm<256,64,2,1><<<dim3(512,1), 256, SM_P64>>>(nullptr, a2, 256,
        wd2, db2, nullptr, out, 64);
}

// round 17
// speedup vs baseline: 1.9571x; 1.1376x over previous
#include <cuda_runtime.h>
#include <cuda_fp16.h>
#include <cstdint>

typedef unsigned short u16;
typedef unsigned int u32;

#define BATCH 32
#define SEQ   2048
#define STATE 64
#define LAT   128
#define ENC   256
#define IND   320
#define NPOS  (BATCH*SEQ)
#define NCHUNK 64
#define CLEN   32

// ---------------- device scratch ----------------
__device__ float g_sum[LAT];
__device__ float g_sumsq[LAT];
__device__ float g_z0[BATCH*LAT];
__device__ float g_Ap0[LAT*LAT];
__device__ float g_Ap1[LAT*LAT];
__device__ float g_lend[NCHUNK*BATCH*LAT];
__device__ float g_sk[NCHUNK*BATCH*LAT];
__device__ u16 g_a1[(size_t)NPOS*ENC];
__device__ u16 g_a2[(size_t)NPOS*ENC];
__device__ u16 g_z1[(size_t)NPOS*LAT];
__device__ __align__(16) u16 g_we0[256*1*72];
__device__ __align__(16) u16 g_we1[256*4*72];
__device__ __align__(16) u16 g_we2[128*4*72];
__device__ __align__(16) u16 g_wd0[256*2*72];
__device__ __align__(16) u16 g_wd1[256*4*72];
__device__ __align__(16) u16 g_wd2[64*4*72];
__device__ __align__(16) u16 g_Aimg[128*2*72];

// ---------------- helpers ----------------
__device__ __forceinline__ u32 smem_u32(const void* p) {
    u32 a;
    asm("{ .reg .u64 t; cvta.to.shared.u64 t, %1; cvt.u32.u64 %0, t; }" : "=r"(a) : "l"(p));
    return a;
}
#define LDSM4(r, a) \
    asm volatile("ldmatrix.sync.aligned.m8n8.x4.shared.b16 {%0,%1,%2,%3}, [%4];" \
        : "=r"((r)[0]), "=r"((r)[1]), "=r"((r)[2]), "=r"((r)[3]) : "r"(a))
#define MMA(d, a, b) \
    asm volatile("mma.sync.aligned.m16n8k16.row.col.f32.f16.f16.f32 " \
        "{%0,%1,%2,%3},{%4,%5,%6,%7},{%8,%9},{%0,%1,%2,%3};" \
        : "+f"((d)[0]), "+f"((d)[1]), "+f"((d)[2]), "+f"((d)[3]) \
        : "r"((a)[0]), "r"((a)[1]), "r"((a)[2]), "r"((a)[3]), "r"((b)[0]), "r"((b)[1]))
#define CPA16(dst, src) asm volatile("cp.async.cg.shared.global [%0], [%1], 16;" :: "r"(dst), "l"(src))
#define CPA_COMMIT()  asm volatile("cp.async.commit_group;" ::: "memory")
#define CPA_WAIT0()   asm volatile("cp.async.wait_group 0;" ::: "memory")
#define CPA_WAIT1()   asm volatile("cp.async.wait_group 1;" ::: "memory")

__device__ __forceinline__ u16 f2h(float v) { __half h = __float2half(v); return *(u16*)&h; }
__device__ __forceinline__ u32 pack2h(float a, float b) {
    return (u32)f2h(a) | ((u32)f2h(b) << 16);
}

// ---------------- fused prep ----------------
__device__ __forceinline__ void prep_one(const float* W, int K, int N, int NT,
                                         u16* oh, int idx) {
    if (idx >= K * N) return;
    int k = idx / N, n = idx % N;
    int NCH = K >> 6;
    int nt = n / NT, nloc = n % NT, c = k >> 6, kl = k & 63;
    size_t d = ((size_t)(nt * NCH + c) * NT + nloc) * 72 + kl;
    oh[d] = f2h(W[idx]);
}

__global__ void k_prep_all(const float* __restrict__ ew0, const float* __restrict__ ew1,
                           const float* __restrict__ ew2, const float* __restrict__ Aw,
                           const float* __restrict__ dw0, const float* __restrict__ dw1,
                           const float* __restrict__ dw2)
{
    int b = blockIdx.x, t = threadIdx.x;
    if (b == 0 && t < LAT) { g_sum[t] = 0.f; g_sumsq[t] = 0.f; }
    if (b < 64)        prep_one(ew0, 64, 256, 128, g_we0, b * 256 + t);
    else if (b < 320)  prep_one(ew1, 256, 256, 128, g_we1, (b - 64) * 256 + t);
    else if (b < 448)  prep_one(ew2, 256, 128, 128, g_we2, (b - 320) * 256 + t);
    else if (b < 512)  prep_one(Aw, 128, 128, 128, g_Aimg, (b - 448) * 256 + t);
    else if (b < 640)  prep_one(dw0, 128, 256, 128, g_wd0, (b - 512) * 256 + t);
    else if (b < 896)  prep_one(dw1, 256, 256, 128, g_wd1, (b - 640) * 256 + t);
    else               prep_one(dw2, 256, 64, 64, g_wd2, (b - 896) * 256 + t);
}

// ---------------- repeated squaring ----------------
__global__ void k_sq(const float* __restrict__ Aw, int step) {
    extern __shared__ float S[];
    const float* src = (step == 0) ? Aw : ((step & 1) ? g_Ap0 : g_Ap1);
    float* dst = (step & 1) ? g_Ap1 : g_Ap0;
    int t = threadIdx.x;
    for (int i = t; i < LAT*LAT; i += 512) S[i] = src[i];
    __syncthreads();
    int base = blockIdx.x * 512 + t;
    int i = base >> 7, j = base & 127;
    float acc = 0.f;
#pragma unroll 8
    for (int k = 0; k < LAT; k++) acc = fmaf(S[i*LAT + k], S[k*LAT + j], acc);
    dst[base] = acc;
}

// ---------------- HMMA GEMM ----------------
template<int K, int NT, int EPI, int ASRC>
__global__ void __launch_bounds__(256, 2) k_gemm(
    const float* __restrict__ A32, const u16* __restrict__ Ax, int lda,
    const u16* __restrict__ Wx,
    const float* __restrict__ bias,
    u16* __restrict__ Ox, float* __restrict__ outF, int ldo)
{
    constexpr int KC  = 64;
    constexpr int NCH = K / KC;
    constexpr int ST  = (NCH > 1) ? 2 : 1;
    constexpr int SMA = 128 * 144;
    constexpr int SMW = NT * 144;
    constexpr int STB = SMA + SMW;
    constexpr int SB  = ST * STB;
    constexpr int MT  = (NT == 128) ? 2 : 1;
    constexpr int WM  = (NT == 128) ? 4 : 8;

    extern __shared__ char sm[];
    u32 sb = smem_u32(sm);
    int tid = threadIdx.x, wid = tid >> 5, l = tid & 31;
    int wm = wid % WM, wn = wid / WM;
    int tile = blockIdx.x, nt = blockIdx.y, nt0 = nt * NT;
    int RW = wm * (MT * 16);

    float* sbias = (float*)(sm + SB);
    float* ssum  = (float*)(sm + SB + 512);
    float* ssq   = (float*)(sm + SB + 1024);
    if (tid < NT) sbias[tid] = bias[nt0 + tid];
    if (EPI == 1 && tid < 128) { ssum[tid] = 0.f; ssq[tid] = 0.f; }

    float acc[MT][8][4];
#pragma unroll
    for (int mt = 0; mt < MT; mt++)
#pragma unroll
        for (int n = 0; n < 8; n++)
#pragma unroll
            for (int i = 0; i < 4; i++) acc[mt][n][i] = 0.f;

    u32 aoff = (RW + (l & 15)) * 144 + (l >> 4) * 16;
    u32 boff = (wn*64 + (l & 7) + ((l >> 4) * 8)) * 144 + (((l >> 3) & 1) * 16);

    auto load_chunk = [&](int c, int s) {
        u32 base = sb + s * STB;
        const u16* wp = Wx + (size_t)(nt * NCH + c) * NT * 72;
#pragma unroll
        for (int i = tid; i < NT * 9; i += 256)
            CPA16(base + SMA + i*16, wp + i*8);
        if (ASRC == 1) {
#pragma unroll
            for (int i = tid; i < 1024; i += 256) {
                int row = i >> 3, seg = i & 7;
                size_t go = (size_t)(tile*128 + row) * lda + c*KC + seg*8;
                CPA16(base + row*144 + seg*16, Ax + go);
            }
        }
    };

    load_chunk(0, 0);
    if (ASRC == 0) {
        int r = tid & 127, kh = (tid >> 7) * 32;
        const float* ap = A32 + (size_t)(tile*128 + r) * lda + kh;
#pragma unroll
        for (int j = 0; j < 4; j++) {
            float4 f0 = *(const float4*)(ap + j*8);
            float4 f1 = *(const float4*)(ap + j*8 + 4);
            float f[8] = {f0.x,f0.y,f0.z,f0.w,f1.x,f1.y,f1.z,f1.w};
            union { u16 us[8]; uint4 u; } ph;
#pragma unroll
            for (int q = 0; q < 8; q++) ph.us[q] = f2h(f[q]);
            *(uint4*)(sm + r*144 + (kh + j*8)*2) = ph.u;
        }
    }
    CPA_COMMIT();

    for (int c = 0; c < NCH; c++) {
        int s = c & (ST - 1);
        bool pre = (ST == 2) && (c + 1 < NCH);
        if (pre) { load_chunk(c + 1, (c + 1) & 1); CPA_COMMIT(); }
        if (pre) CPA_WAIT1(); else CPA_WAIT0();
        __syncthreads();

        u32 sA = sb + s * STB, sW = sA + SMA;
#pragma unroll
        for (int ks = 0; ks < 4; ks++) {
            int k2 = ks * 32;
            u32 af[MT][4], bf[4][4];
#pragma unroll
            for (int mt = 0; mt < MT; mt++) LDSM4(af[mt], sA + aoff + mt*2304 + k2);
#pragma unroll
            for (int p = 0; p < 4; p++)     LDSM4(bf[p], sW + boff + p*2304 + k2);
#pragma unroll
            for (int mt = 0; mt < MT; mt++)
#pragma unroll
                for (int p = 0; p < 4; p++) {
                    MMA(acc[mt][2*p],   af[mt], bf[p]);
                    MMA(acc[mt][2*p+1], af[mt], &bf[p][2]);
                }
        }
        __syncthreads();
    }

    int g = l >> 2, tg = l & 3;
#pragma unroll
    for (int n = 0; n < 8; n++) {
        int colL = wn*64 + n*8 + tg*2;
        float b0 = sbias[colL], b1 = sbias[colL + 1];
        float s0 = 0.f, q0 = 0.f, s1 = 0.f, q1 = 0.f;
#pragma unroll
        for (int mt = 0; mt < MT; mt++) {
            int row = tile*128 + RW + mt*16 + g;
            float v0 = acc[mt][n][0] + b0, v1 = acc[mt][n][1] + b1;
            float v2 = acc[mt][n][2] + b0, v3 = acc[mt][n][3] + b1;
            if (EPI != 2) {
                v0 = fmaxf(v0, 0.f); v1 = fmaxf(v1, 0.f);
                v2 = fmaxf(v2, 0.f); v3 = fmaxf(v3, 0.f);
            }
            if (EPI == 1) {
                s0 += v0 + v2; q0 += v0*v0 + v2*v2;
                s1 += v1 + v3; q1 += v1*v1 + v3*v3;
                if (((tile & 15) == 0) && g == 0 && wm == 0 && mt == 0) {
                    g_z0[(tile >> 4) * LAT + colL]     = v0;
                    g_z0[(tile >> 4) * LAT + colL + 1] = v1;
                }
            } else if (EPI == 0) {
                size_t o0 = (size_t)row * ldo + nt0 + colL;
                size_t o1 = (size_t)(row + 8) * ldo + nt0 + colL;
                *(u32*)&Ox[o0] = pack2h(v0, v1);
                *(u32*)&Ox[o1] = pack2h(v2, v3);
            } else {
                *(float2*)&outF[(size_t)row * ldo + nt0 + colL]       = make_float2(v0, v1);
                *(float2*)&outF[(size_t)(row + 8) * ldo + nt0 + colL] = make_float2(v2, v3);
            }
        }
        if (EPI == 1) {
            // reduce across the 8 lanes sharing this column (stride-4 lane groups)
#pragma unroll
            for (int d = 4; d < 32; d <<= 1) {
                s0 += __shfl_xor_sync(0xffffffffu, s0, d);
                q0 += __shfl_xor_sync(0xffffffffu, q0, d);
                s1 += __shfl_xor_sync(0xffffffffu, s1, d);
                q1 += __shfl_xor_sync(0xffffffffu, q1, d);
            }
            if (g == 0) {
                atomicAdd(&ssum[colL],     s0);
                atomicAdd(&ssq[colL],      q0);
                atomicAdd(&ssum[colL + 1], s1);
                atomicAdd(&ssq[colL + 1],  q1);
            }
        }
    }
    if (EPI == 1) {
        __syncthreads();
        if (tid < 128) {
            atomicAdd(&g_sum[tid],   ssum[tid]);
            atomicAdd(&g_sumsq[tid], ssq[tid]);
        }
    }
}

// ---------------- MMA scan with bu cp.async prefetch ----------------
template<int PASS>
__global__ void __launch_bounds__(256) k_scan(
    const float* __restrict__ in, const float* __restrict__ Bd)
{
    constexpr int SM_A   = 0;
    constexpr int SM_H   = 36864;
    constexpr int SM_BU  = 45568;
    constexpr int BUST   = 8448;
    constexpr int SM_D   = 62464;
    extern __shared__ char sm[];
    u32 sb = smem_u32(sm);

    int tid = threadIdx.x, wid = tid >> 5, l = tid & 31;
    int chunk = blockIdx.x, b0 = blockIdx.y * 16;
    int g = l >> 2, tg = l & 3;
    int wcol = wid * 16;
    int t0 = chunk * CLEN;

    auto loadBU = [&](int t, int s) {
        u32 base = sb + SM_BU + s * BUST;
#pragma unroll
        for (int i = tid; i < 512; i += 256) {
            int row = i >> 5, seg = i & 31;
            const float* src = in + ((size_t)(b0 + row) * SEQ + t) * IND + (STATE + LAT) + seg * 4;
            CPA16(base + row * 528 + seg * 16, src);
        }
    };

    for (int i = tid; i < 2304; i += 256)
        CPA16(sb + SM_A + i*16, g_Aimg + i*8);
    loadBU(t0, 0);
    if (tid < 128) ((float*)(sm + SM_D))[tid] = fminf(fmaxf(Bd[tid], -0.95f), 0.95f);
    CPA_COMMIT();

    {
        int row = tid >> 4, cg = (tid & 15) * 8;
        u32 off = SM_H + row * 272 + cg * 2;
        if (PASS == 1) {
            const float* sp = &g_sk[(size_t)(chunk * BATCH + b0 + row) * LAT + cg];
            float4 f0 = *(const float4*)sp, f1 = *(const float4*)(sp + 4);
            *(uint4*)(sm + off) = make_uint4(pack2h(f0.x, f0.y), pack2h(f0.z, f0.w),
                                             pack2h(f1.x, f1.y), pack2h(f1.z, f1.w));
        } else {
            *(uint4*)(sm + off) = make_uint4(0, 0, 0, 0);
        }
    }
    CPA_WAIT0();
    __syncthreads();

    u32 bf[8][4];
    u32 boffb = (u32)((wcol + (l & 7) + ((l >> 4) * 8)) * 144 + (((l >> 3) & 1) * 16));
#pragma unroll
    for (int ks = 0; ks < 8; ks++)
        LDSM4(bf[ks], sb + SM_A + (ks >> 2) * 18432 + boffb + (ks & 3) * 32);

    const float* sd = (const float*)(sm + SM_D);
    float da0 = sd[wcol + tg*2],     da1 = sd[wcol + tg*2 + 1];
    float db0 = sd[wcol + 8 + tg*2], db1 = sd[wcol + 8 + tg*2 + 1];
    u32 aoff = (u32)((l & 15) * 272 + (l >> 4) * 16);
    int cur = 0, buf = 0;
    float c0[4], c1[4];

    for (int t = t0; t < t0 + CLEN; t++) {
        bool pre = (t + 1 < t0 + CLEN);
        if (pre) { loadBU(t + 1, buf ^ 1); CPA_COMMIT(); }
        if (pre) CPA_WAIT1(); else CPA_WAIT0();
        __syncthreads();

        {
            const char* bub = sm + SM_BU + buf * BUST;
            float2 a0 = *(float2*)(bub + g * 528 + (wcol + tg*2) * 4);
            float2 a1 = *(float2*)(bub + (g + 8) * 528 + (wcol + tg*2) * 4);
            float2 a2 = *(float2*)(bub + g * 528 + (wcol + 8 + tg*2) * 4);
            float2 a3 = *(float2*)(bub + (g + 8) * 528 + (wcol + 8 + tg*2) * 4);
            c0[0] = a0.x * da0; c0[1] = a0.y * da1; c0[2] = a1.x * da0; c0[3] = a1.y * da1;
            c1[0] = a2.x * db0; c1[1] = a2.y * db1; c1[2] = a3.x * db0; c1[3] = a3.y * db1;
        }

        u32 hbase = sb + SM_H + cur * 4352;
#pragma unroll
        for (int ks = 0; ks < 8; ks++) {
            u32 af[4];
            LDSM4(af, hbase + aoff + ks * 32);
            MMA(c0, af, bf[ks]);
            MMA(c1, af, &bf[ks][2]);
        }

        int hno = SM_H + (cur ^ 1) * 4352;
        u32 p00 = pack2h(c0[0], c0[1]), p01 = pack2h(c0[2], c0[3]);
        u32 p10 = pack2h(c1[0], c1[1]), p11 = pack2h(c1[2], c1[3]);
        *(u32*)(sm + hno + g * 272 + (wcol + tg*2) * 2)           = p00;
        *(u32*)(sm + hno + (g + 8) * 272 + (wcol + tg*2) * 2)     = p01;
        *(u32*)(sm + hno + g * 272 + (wcol + 8 + tg*2) * 2)       = p10;
        *(u32*)(sm + hno + (g + 8) * 272 + (wcol + 8 + tg*2) * 2) = p11;
        if (PASS == 1) {
            size_t r0 = ((size_t)(b0 + g) * SEQ + t) * LAT;
            size_t r1 = ((size_t)(b0 + g + 8) * SEQ + t) * LAT;
            *(u32*)&g_z1[r0 + wcol + tg*2]     = p00;
            *(u32*)&g_z1[r1 + wcol + tg*2]     = p01;
            *(u32*)&g_z1[r0 + wcol + 8 + tg*2] = p10;
            *(u32*)&g_z1[r1 + wcol + 8 + tg*2] = p11;
        }
        __syncthreads();
        cur ^= 1; buf ^= 1;
    }

    if (PASS == 0) {
        size_t r0 = (size_t)(chunk * BATCH + b0 + g) * LAT;
        size_t r1 = (size_t)(chunk * BATCH + b0 + g + 8) * LAT;
        *(float2*)&g_lend[r0 + wcol + tg*2]     = make_float2(c0[0], c0[1]);
        *(float2*)&g_lend[r1 + wcol + tg*2]     = make_float2(c0[2], c0[3]);
        *(float2*)&g_lend[r0 + wcol + 8 + tg*2] = make_float2(c1[0], c1[1]);
        *(float2*)&g_lend[r1 + wcol + 8 + tg*2] = make_float2(c1[2], c1[3]);
    }
}

// ---------------- boundary scan (BN finalize fused) ----------------
__global__ void __launch_bounds__(128) k_bound(const float* __restrict__ gamma,
                                               const float* __restrict__ beta)
{
    extern __shared__ float smf[];
    float* As = smf;
    float* sv = smf + LAT * LAT;
    int j = threadIdx.x;
    int b = blockIdx.x;

    float inv = 1.f / (float)NPOS;
    float m  = g_sum[j] * inv;
    float v  = g_sumsq[j] * inv - m * m;
    float rs = rsqrtf(v + 1e-5f);
    float s = (g_z0[b * LAT + j] - m) * rs * gamma[j] + beta[j];

    for (int idx = j; idx < LAT * LAT; idx += 128) As[idx] = g_Ap0[idx];
    __syncthreads();
    for (int k = 0; k < NCHUNK; k++) {
        g_sk[(k * BATCH + b) * LAT + j] = s;
        sv[j] = s;
        __syncthreads();
        float acc = g_lend[(k * BATCH + b) * LAT + j];
#pragma unroll 8
        for (int m4 = 0; m4 < LAT; m4 += 4) {
            float a0 = As[(m4+0)*LAT + j], a1 = As[(m4+1)*LAT + j];
            float a2 = As[(m4+2)*LAT + j], a3 = As[(m4+3)*LAT + j];
            float4 h = *(const float4*)&sv[m4];
            acc = fmaf(h.x, a0, fmaf(h.y, a1, fmaf(h.z, a2, fmaf(h.w, a3, acc))));
        }
        __syncthreads();
        s = acc;
    }
}

// ---------------- launch ----------------
extern "C" void kernel_launch(void* const* d_in, const int* in_sizes, int n_in,
                              void* d_out, int out_size)
{
    const float* in  = (const float*)d_in[0];
    const float* ew0 = (const float*)d_in[1];
    const float* eb0 = (const float*)d_in[2];
    const float* ew1 = (const float*)d_in[3];
    const float* eb1 = (const float*)d_in[4];
    const float* ew2 = (const float*)d_in[5];
    const float* eb2 = (const float*)d_in[6];
    const float* gam = (const float*)d_in[7];
    const float* bet = (const float*)d_in[8];
    const float* Aw  = (const float*)d_in[9];
    const float* Bd  = (const float*)d_in[10];
    const float* dw0 = (const float*)d_in[11];
    const float* db0 = (const float*)d_in[12];
    const float* dw1 = (const float*)d_in[13];
    const float* db1 = (const float*)d_in[14];
    const float* dw2 = (const float*)d_in[15];
    const float* db2 = (const float*)d_in[16];
    float* out = (float*)d_out;

    u16 *a1, *a2, *z1, *we0, *we1, *we2, *wd0, *wd1, *wd2;
    cudaGetSymbolAddress((void**)&a1, g_a1);
    cudaGetSymbolAddress((void**)&a2, g_a2);
    cudaGetSymbolAddress((void**)&z1, g_z1);
    cudaGetSymbolAddress((void**)&we0, g_we0);
    cudaGetSymbolAddress((void**)&we1, g_we1);
    cudaGetSymbolAddress((void**)&we2, g_we2);
    cudaGetSymbolAddress((void**)&wd0, g_wd0);
    cudaGetSymbolAddress((void**)&wd1, g_wd1);
    cudaGetSymbolAddress((void**)&wd2, g_wd2);

    const int SM_L0   = 38400;
    const int SM_P128 = 75264;
    const int SM_P64  = 56832;
    const int SMSC    = 62976;

    cudaFuncSetAttribute(k_sq,    cudaFuncAttributeMaxDynamicSharedMemorySize, 65536);
    cudaFuncSetAttribute(k_bound, cudaFuncAttributeMaxDynamicSharedMemorySize, 66560);
    cudaFuncSetAttribute(k_scan<0>, cudaFuncAttributeMaxDynamicSharedMemorySize, SMSC);
    cudaFuncSetAttribute(k_scan<1>, cudaFuncAttributeMaxDynamicSharedMemorySize, SMSC);
    cudaFuncSetAttribute(k_gemm<64,128,0,0>,  cudaFuncAttributeMaxDynamicSharedMemorySize, SM_L0);
    cudaFuncSetAttribute(k_gemm<256,128,0,1>, cudaFuncAttributeMaxDynamicSharedMemorySize, SM_P128);
    cudaFuncSetAttribute(k_gemm<256,128,1,1>, cudaFuncAttributeMaxDynamicSharedMemorySize, SM_P128);
    cudaFuncSetAttribute(k_gemm<128,128,0,1>, cudaFuncAttributeMaxDynamicSharedMemorySize, SM_P128);
    cudaFuncSetAttribute(k_gemm<256,64,2,1>,  cudaFuncAttributeMaxDynamicSharedMemorySize, SM_P64);

    static cudaStream_t sB = nullptr;
    static cudaEvent_t evP = nullptr, evB = nullptr;
    if (!sB) {
        cudaStreamCreateWithFlags(&sB, cudaStreamNonBlocking);
        cudaEventCreateWithFlags(&evP, cudaEventDisableTiming);
        cudaEventCreateWithFlags(&evB, cudaEventDisableTiming);
    }

    // ---- single fused prep ----
    k_prep_all<<<960, 256>>>(ew0, ew1, ew2, Aw, dw0, dw1, dw2);
    cudaEventRecord(evP, 0);

    // ---- stream 0: encoder ----
    k_gemm<64,128,0,0><<<dim3(512,2), 256, SM_L0>>>(in, nullptr, IND,
        we0, eb0, a1, nullptr, 256);
    k_gemm<256,128,0,1><<<dim3(512,2), 256, SM_P128>>>(nullptr, a1, 256,
        we1, eb1, a2, nullptr, 256);
    k_gemm<256,128,1,1><<<dim3(512,1), 256, SM_P128>>>(nullptr, a2, 256,
        we2, eb2, nullptr, nullptr, 0);

    // ---- stream B: pass0 + A^32 chain ----
    cudaStreamWaitEvent(sB, evP, 0);
    k_scan<0><<<dim3(NCHUNK, 2), 256, SMSC, sB>>>(in, Bd);
    for (int s = 0; s < 5; s++) k_sq<<<32, 512, 65536, sB>>>(Aw, s);
    cudaEventRecord(evB, sB);

    // ---- join, serial tail ----
    cudaStreamWaitEvent(0, evB, 0);
    k_bound<<<BATCH, 128, 66560>>>(gam, bet);
    k_scan<1><<<dim3(NCHUNK, 2), 256, SMSC>>>(in, Bd);
    k_gemm<128,128,0,1><<<dim3(512,2), 256, SM_P128>>>(nullptr, z1, 128,
        wd0, db0, a1, nullptr, 256);
    k_gemm<256,128,0,1><<<dim3(512,2), 256, SM_P128>>>(nullptr, a1, 256,
        wd1, db1, a2, nullptr, 256);
    k_gemm<256,64,2,1><<<dim3(512,1), 256, SM_P64>>>(nullptr, a2, 256,
        wd2, db2, nullptr, out, 64);
}